// round 2
// baseline (speedup 1.0000x reference)
#include <cuda_runtime.h>
#include <cuda_bf16.h>
#include <math.h>

#define BSZ 2
#define SEQ 2048
#define DIM 2048
#define NH  16
#define HD  128
#define MROWS (BSZ*SEQ)          // 4096

// ---------------- scratch (static device globals; no allocation) -----------
__device__ float g_qlin[(size_t)MROWS * DIM];
__device__ float g_klin[(size_t)MROWS * DIM];
__device__ float g_vlin[(size_t)MROWS * DIM];
__device__ float g_Q[(size_t)BSZ * NH * SEQ * HD];
__device__ float g_K[(size_t)BSZ * NH * SEQ * HD];
__device__ float g_V[(size_t)BSZ * NH * SEQ * HD];
__device__ float g_attn[(size_t)MROWS * DIM];

// ---------------- NT GEMM: C[m,n] = sum_k A[m,k] * B[n,k] ------------------
#define BM 64
#define BN 64
#define BK 32

__global__ __launch_bounds__(256) void gemm_nt_kernel(
    const float* __restrict__ A, const float* __restrict__ B,
    float* __restrict__ C, int Mdim, int Ndim, int Kdim)
{
    __shared__ float As[BM][BK + 1];
    __shared__ float Bs[BN][BK + 1];

    const int t  = threadIdx.x;          // 0..255
    const int tx = t & 15;               // 0..15 -> 4 cols each
    const int ty = t >> 4;               // 0..15 -> 4 rows each
    const int row0 = blockIdx.y * BM;
    const int col0 = blockIdx.x * BN;

    float acc[4][4];
#pragma unroll
    for (int i = 0; i < 4; i++)
#pragma unroll
        for (int j = 0; j < 4; j++) acc[i][j] = 0.f;

    for (int k0 = 0; k0 < Kdim; k0 += BK) {
#pragma unroll
        for (int i = 0; i < (BM * BK) / 256; i++) {
            int idx = t + i * 256;
            int r = idx / BK, c = idx % BK;
            As[r][c] = A[(size_t)(row0 + r) * Kdim + k0 + c];
            Bs[r][c] = B[(size_t)(col0 + r) * Kdim + k0 + c];
        }
        __syncthreads();
#pragma unroll
        for (int kk = 0; kk < BK; kk++) {
            float a[4], b[4];
#pragma unroll
            for (int i = 0; i < 4; i++) a[i] = As[ty * 4 + i][kk];
#pragma unroll
            for (int j = 0; j < 4; j++) b[j] = Bs[tx * 4 + j][kk];
#pragma unroll
            for (int i = 0; i < 4; i++)
#pragma unroll
                for (int j = 0; j < 4; j++)
                    acc[i][j] = fmaf(a[i], b[j], acc[i][j]);
        }
        __syncthreads();
    }

#pragma unroll
    for (int i = 0; i < 4; i++)
#pragma unroll
        for (int j = 0; j < 4; j++)
            C[(size_t)(row0 + ty * 4 + i) * Ndim + col0 + tx * 4 + j] = acc[i][j];
}

// ------------- RoPE (q,k) + transpose to [B,H,S,HD]; V transpose -----------
__global__ __launch_bounds__(256) void rope_transpose_kernel(
    const float* __restrict__ qlin, const float* __restrict__ klin,
    const float* __restrict__ vlin,
    const float* __restrict__ cosT, const float* __restrict__ sinT,
    float* __restrict__ Q, float* __restrict__ K, float* __restrict__ V)
{
    int idx = blockIdx.x * blockDim.x + threadIdx.x;   // over B*S*NH*(HD/2)
    const int HDH = HD / 2;
    int d2 = idx % HDH;
    int h  = (idx / HDH) % NH;
    int s  = (idx / (HDH * NH)) % SEQ;
    int b  = idx / (HDH * NH * SEQ);

    size_t m   = (size_t)b * SEQ + s;
    size_t src = m * DIM + h * HD + 2 * d2;
    float c  = cosT[s * HDH + d2];
    float sn = sinT[s * HDH + d2];

    size_t dst = (((size_t)(b * NH + h) * SEQ + s) * HD) + 2 * d2;

    float q0 = qlin[src], q1 = qlin[src + 1];
    Q[dst]     = q0 * c - q1 * sn;
    Q[dst + 1] = q0 * sn + q1 * c;

    float k0 = klin[src], k1 = klin[src + 1];
    K[dst]     = k0 * c - k1 * sn;
    K[dst + 1] = k0 * sn + k1 * c;

    V[dst]     = vlin[src];
    V[dst + 1] = vlin[src + 1];
}

// ---------------- Flash attention (causal, fp32) ---------------------------
#define BQ  64
#define BKV 64
#define QSTR (HD + 1)     // 129, padded smem row stride
#define PSTR (BKV + 1)    // 65

// dynamic smem: Q(64x129) + K(64x129) + V(64x129) + P(64x65) floats
#define FLASH_SMEM_FLOATS (3 * BQ * QSTR + BQ * PSTR)
#define FLASH_SMEM_BYTES  (FLASH_SMEM_FLOATS * 4)

__global__ __launch_bounds__(256) void flash_attn_kernel(
    const float* __restrict__ Q, const float* __restrict__ K,
    const float* __restrict__ V, float* __restrict__ Out)
{
    extern __shared__ float sm[];
    float* Qs = sm;
    float* Ks = Qs + BQ * QSTR;
    float* Vs = Ks + BKV * QSTR;
    float* Ps = Vs + BKV * QSTR;

    const int bh = blockIdx.x;            // b*NH + h
    const int qt = blockIdx.y;            // q tile index
    const int t  = threadIdx.x;           // 256
    const int tx = t & 15;                // score cols 4x ; out cols 8x
    const int ty = t >> 4;                // rows 4x

    const float scale = 0.08838834764831845f;   // 1/sqrt(128)

    const float* Qb = Q + ((size_t)bh * SEQ + (size_t)qt * BQ) * HD;
#pragma unroll
    for (int i = 0; i < (BQ * HD) / 256; i++) {
        int idx = t + i * 256;
        Qs[(idx >> 7) * QSTR + (idx & 127)] = Qb[idx];
    }

    float m_i[4], l_i[4], o[4][8];
#pragma unroll
    for (int i = 0; i < 4; i++) {
        m_i[i] = -INFINITY; l_i[i] = 0.f;
#pragma unroll
        for (int j = 0; j < 8; j++) o[i][j] = 0.f;
    }
    __syncthreads();

    for (int kt = 0; kt <= qt; kt++) {
        const float* Kb = K + ((size_t)bh * SEQ + (size_t)kt * BKV) * HD;
        const float* Vb = V + ((size_t)bh * SEQ + (size_t)kt * BKV) * HD;
#pragma unroll
        for (int i = 0; i < (BKV * HD) / 256; i++) {
            int idx = t + i * 256;
            int r = idx >> 7, c = idx & 127;
            Ks[r * QSTR + c] = Kb[idx];
            Vs[r * QSTR + c] = Vb[idx];
        }
        __syncthreads();

        // scores: 4x4 per thread over 64x64 tile
        float sc[4][4];
#pragma unroll
        for (int i = 0; i < 4; i++)
#pragma unroll
            for (int j = 0; j < 4; j++) sc[i][j] = 0.f;

        for (int kk = 0; kk < HD; kk++) {
            float a[4], b[4];
#pragma unroll
            for (int i = 0; i < 4; i++) a[i] = Qs[(ty * 4 + i) * QSTR + kk];
#pragma unroll
            for (int j = 0; j < 4; j++) b[j] = Ks[(tx * 4 + j) * QSTR + kk];
#pragma unroll
            for (int i = 0; i < 4; i++)
#pragma unroll
                for (int j = 0; j < 4; j++)
                    sc[i][j] = fmaf(a[i], b[j], sc[i][j]);
        }

        // scale + causal mask (only diagonal tile has masked entries)
        if (kt == qt) {
#pragma unroll
            for (int i = 0; i < 4; i++) {
                int rg = ty * 4 + i;
#pragma unroll
                for (int j = 0; j < 4; j++) {
                    int cg = tx * 4 + j;
                    sc[i][j] = (cg > rg) ? -INFINITY : sc[i][j] * scale;
                }
            }
        } else {
#pragma unroll
            for (int i = 0; i < 4; i++)
#pragma unroll
                for (int j = 0; j < 4; j++) sc[i][j] *= scale;
        }

        // online softmax per row
#pragma unroll
        for (int i = 0; i < 4; i++) {
            float mloc = fmaxf(fmaxf(sc[i][0], sc[i][1]), fmaxf(sc[i][2], sc[i][3]));
#pragma unroll
            for (int off = 1; off < 16; off <<= 1)
                mloc = fmaxf(mloc, __shfl_xor_sync(0xffffffffu, mloc, off));

            float m_new = fmaxf(m_i[i], mloc);
            float alpha = __expf(m_i[i] - m_new);   // 0 when m_i = -inf

            float p[4], rs = 0.f;
#pragma unroll
            for (int j = 0; j < 4; j++) {
                p[j] = __expf(sc[i][j] - m_new);
                rs += p[j];
            }
#pragma unroll
            for (int off = 1; off < 16; off <<= 1)
                rs += __shfl_xor_sync(0xffffffffu, rs, off);

            l_i[i] = l_i[i] * alpha + rs;
            m_i[i] = m_new;
#pragma unroll
            for (int j = 0; j < 8; j++) o[i][j] *= alpha;
#pragma unroll
            for (int j = 0; j < 4; j++)
                Ps[(ty * 4 + i) * PSTR + tx * 4 + j] = p[j];
        }
        __syncthreads();

        // O += P @ V : thread owns rows ty*4+i, out cols tx*8+j
        for (int c = 0; c < BKV; c++) {
            float pv[4], vv[8];
#pragma unroll
            for (int i = 0; i < 4; i++) pv[i] = Ps[(ty * 4 + i) * PSTR + c];
#pragma unroll
            for (int j = 0; j < 8; j++) vv[j] = Vs[c * QSTR + tx * 8 + j];
#pragma unroll
            for (int i = 0; i < 4; i++)
#pragma unroll
                for (int j = 0; j < 8; j++)
                    o[i][j] = fmaf(pv[i], vv[j], o[i][j]);
        }
        __syncthreads();   // before next tile overwrites Ks/Vs/Ps
    }

    // write to [B, S, H, HD] (= [M, DIM] row layout for final GEMM)
    const int b = bh / NH, h = bh % NH;
#pragma unroll
    for (int i = 0; i < 4; i++) {
        int s = qt * BQ + ty * 4 + i;
        float inv_l = 1.0f / l_i[i];
        size_t base = ((size_t)(b * SEQ + s)) * DIM + h * HD + tx * 8;
#pragma unroll
        for (int j = 0; j < 8; j++)
            g_attn[base + j] = o[i][j] * inv_l;
    }
    (void)Out;
}

// ---------------------------------------------------------------------------
extern "C" void kernel_launch(void* const* d_in, const int* in_sizes, int n_in,
                              void* d_out, int out_size)
{
    const float* x    = (const float*)d_in[0];
    const float* wq   = (const float*)d_in[1];
    const float* wk   = (const float*)d_in[2];
    const float* wv   = (const float*)d_in[3];
    const float* wo   = (const float*)d_in[4];
    const float* fcos = (const float*)d_in[5];
    const float* fsin = (const float*)d_in[6];
    // d_in[7] = mask (causal; handled analytically)
    float* out = (float*)d_out;

    float *qlin, *klin, *vlin, *Qp, *Kp, *Vp, *attn;
    cudaGetSymbolAddress((void**)&qlin, g_qlin);
    cudaGetSymbolAddress((void**)&klin, g_klin);
    cudaGetSymbolAddress((void**)&vlin, g_vlin);
    cudaGetSymbolAddress((void**)&Qp,   g_Q);
    cudaGetSymbolAddress((void**)&Kp,   g_K);
    cudaGetSymbolAddress((void**)&Vp,   g_V);
    cudaGetSymbolAddress((void**)&attn, g_attn);

    dim3 gemmGrid(DIM / BN, MROWS / BM);

    gemm_nt_kernel<<<gemmGrid, 256>>>(x, wq, qlin, MROWS, DIM, DIM);
    gemm_nt_kernel<<<gemmGrid, 256>>>(x, wk, klin, MROWS, DIM, DIM);
    gemm_nt_kernel<<<gemmGrid, 256>>>(x, wv, vlin, MROWS, DIM, DIM);

    int ropeElems = BSZ * SEQ * NH * (HD / 2);
    rope_transpose_kernel<<<ropeElems / 256, 256>>>(qlin, klin, vlin,
                                                    fcos, fsin, Qp, Kp, Vp);

    cudaFuncSetAttribute(flash_attn_kernel,
                         cudaFuncAttributeMaxDynamicSharedMemorySize,
                         FLASH_SMEM_BYTES);
    flash_attn_kernel<<<dim3(BSZ * NH, SEQ / BQ), 256, FLASH_SMEM_BYTES>>>(
        Qp, Kp, Vp, attn);

    gemm_nt_kernel<<<gemmGrid, 256>>>(attn, wo, out, MROWS, DIM, DIM);
}

// round 4
// speedup vs baseline: 1.7084x; 1.7084x over previous
#include <cuda_runtime.h>
#include <cuda_bf16.h>
#include <math.h>
#include <stdint.h>

#define BSZ 2
#define SEQ 2048
#define DIM 2048
#define NH  16
#define HD  128
#define MROWS (BSZ*SEQ)          // 4096

// ---------------- scratch (static device globals; no allocation) -----------
__device__ float g_qlin[(size_t)MROWS * DIM];
__device__ float g_klin[(size_t)MROWS * DIM];
__device__ float g_vlin[(size_t)MROWS * DIM];
__device__ float g_Q[(size_t)BSZ * NH * SEQ * HD];
__device__ float g_K[(size_t)BSZ * NH * SEQ * HD];
__device__ float g_V[(size_t)BSZ * NH * SEQ * HD];
__device__ float g_attn[(size_t)MROWS * DIM];

// bf16 split-precision operands
__device__ __nv_bfloat16 g_xh[(size_t)MROWS * DIM];
__device__ __nv_bfloat16 g_xl[(size_t)MROWS * DIM];
__device__ __nv_bfloat16 g_wqh[(size_t)DIM * DIM];
__device__ __nv_bfloat16 g_wql[(size_t)DIM * DIM];
__device__ __nv_bfloat16 g_wkh[(size_t)DIM * DIM];
__device__ __nv_bfloat16 g_wkl[(size_t)DIM * DIM];
__device__ __nv_bfloat16 g_wvh[(size_t)DIM * DIM];
__device__ __nv_bfloat16 g_wvl[(size_t)DIM * DIM];
__device__ __nv_bfloat16 g_woh[(size_t)DIM * DIM];
__device__ __nv_bfloat16 g_wol[(size_t)DIM * DIM];
__device__ __nv_bfloat16 g_ah[(size_t)MROWS * DIM];
__device__ __nv_bfloat16 g_al[(size_t)MROWS * DIM];

// ======================= helpers ==========================================
__device__ __forceinline__ uint32_t smem_u32(const void* p) {
    uint32_t a;
    asm("{ .reg .u64 t; cvta.to.shared.u64 t, %1; cvt.u32.u64 %0, t; }"
        : "=r"(a) : "l"(p));
    return a;
}
__device__ __forceinline__ void cp16(uint32_t saddr, const void* g) {
    asm volatile("cp.async.ca.shared.global [%0], [%1], 16;"
                 :: "r"(saddr), "l"(g));
}
#define CP_COMMIT() asm volatile("cp.async.commit_group;" ::: "memory")
#define CP_WAIT(n)  asm volatile("cp.async.wait_group %0;" :: "n"(n) : "memory")

__device__ __forceinline__ void ldm_x4(uint32_t* d, uint32_t addr) {
    asm volatile("ldmatrix.sync.aligned.m8n8.x4.shared.b16 {%0,%1,%2,%3}, [%4];"
                 : "=r"(d[0]), "=r"(d[1]), "=r"(d[2]), "=r"(d[3]) : "r"(addr));
}
__device__ __forceinline__ void mma_bf16(float* c, const uint32_t* a,
                                         uint32_t b0, uint32_t b1) {
    asm volatile(
        "mma.sync.aligned.m16n8k16.row.col.f32.bf16.bf16.f32 "
        "{%0,%1,%2,%3}, {%4,%5,%6,%7}, {%8,%9}, {%0,%1,%2,%3};"
        : "+f"(c[0]), "+f"(c[1]), "+f"(c[2]), "+f"(c[3])
        : "r"(a[0]), "r"(a[1]), "r"(a[2]), "r"(a[3]), "r"(b0), "r"(b1));
}

// =================== split fp32 -> (hi, lo) bf16 ===========================
__global__ __launch_bounds__(256) void split_kernel(
    const float4* __restrict__ in, __nv_bfloat162* __restrict__ hi,
    __nv_bfloat162* __restrict__ lo, int n4)
{
    int i = blockIdx.x * blockDim.x + threadIdx.x;
    if (i >= n4) return;
    float4 v = in[i];
    __nv_bfloat16 h0 = __float2bfloat16(v.x);
    __nv_bfloat16 h1 = __float2bfloat16(v.y);
    __nv_bfloat16 h2 = __float2bfloat16(v.z);
    __nv_bfloat16 h3 = __float2bfloat16(v.w);
    __nv_bfloat16 l0 = __float2bfloat16(v.x - __bfloat162float(h0));
    __nv_bfloat16 l1 = __float2bfloat16(v.y - __bfloat162float(h1));
    __nv_bfloat16 l2 = __float2bfloat16(v.z - __bfloat162float(h2));
    __nv_bfloat16 l3 = __float2bfloat16(v.w - __bfloat162float(h3));
    __nv_bfloat162 p0; p0.x = h0; p0.y = h1;
    __nv_bfloat162 p1; p1.x = h2; p1.y = h3;
    __nv_bfloat162 q0; q0.x = l0; q0.y = l1;
    __nv_bfloat162 q1; q1.x = l2; q1.y = l3;
    hi[2 * i] = p0; hi[2 * i + 1] = p1;
    lo[2 * i] = q0; lo[2 * i + 1] = q1;
}

// =============== mma.sync NT GEMM (split bf16, fp32 accum) =================
// C[m,n] = sum_k (Ah+Al)[m,k] * (Bh+Bl)[n,k], omitting Al*Bl
// CTA tile 128x128, 8 warps -> each 64x32. BK=32 halves. cp.async 2-stage.
#define GSTR 40                        // smem row stride in halves
#define TILEB (128 * GSTR * 2)         // 10240 bytes per operand tile
#define STAGEB (4 * TILEB)             // Ah,Al,Bh,Bl = 40960 bytes
#define GEMM_SMEM (2 * STAGEB)         // 81920 bytes

__device__ __forceinline__ void gemm_load_chunk(
    uint32_t sbase,
    const __nv_bfloat16* __restrict__ Ah, const __nv_bfloat16* __restrict__ Al,
    const __nv_bfloat16* __restrict__ Bh, const __nv_bfloat16* __restrict__ Bl,
    int row0, int col0, int k0, int Kdim, int tid)
{
#pragma unroll
    for (int i = 0; i < 2; ++i) {
        int v = tid + i * 256;                     // 0..511
        int r = v >> 2, cv = v & 3;
        uint32_t soff = (uint32_t)(r * GSTR + cv * 8) * 2;
        size_t gA = (size_t)(row0 + r) * Kdim + k0 + cv * 8;
        size_t gB = (size_t)(col0 + r) * Kdim + k0 + cv * 8;
        cp16(sbase + soff,             Ah + gA);
        cp16(sbase + TILEB + soff,     Al + gA);
        cp16(sbase + 2 * TILEB + soff, Bh + gB);
        cp16(sbase + 3 * TILEB + soff, Bl + gB);
    }
}

__global__ __launch_bounds__(256) void gemm_mma_kernel(
    const __nv_bfloat16* __restrict__ Ah, const __nv_bfloat16* __restrict__ Al,
    const __nv_bfloat16* __restrict__ Bh, const __nv_bfloat16* __restrict__ Bl,
    float* __restrict__ C, int Mdim, int Ndim, int Kdim)
{
    extern __shared__ char smem[];
    uint32_t sm0 = smem_u32(smem);

    const int tid  = threadIdx.x;
    const int wid  = tid >> 5;
    const int lane = tid & 31;
    const int wr = wid >> 2, wc = wid & 3;
    const int m0w = wr * 64, n0w = wc * 32;
    const int row0 = blockIdx.y * 128;
    const int col0 = blockIdx.x * 128;

    // ldmatrix per-lane fragment addressing
    const int g  = lane >> 3;
    const int fr = (g & 1) * 8 + (lane & 7);   // row within 16
    const int fc = (g >> 1) * 8;               // col-half within 16

    float acc[4][4][4];
#pragma unroll
    for (int a = 0; a < 4; a++)
#pragma unroll
        for (int b = 0; b < 4; b++)
#pragma unroll
            for (int d = 0; d < 4; d++) acc[a][b][d] = 0.f;

    const int nchunk = Kdim / 32;

    gemm_load_chunk(sm0, Ah, Al, Bh, Bl, row0, col0, 0, Kdim, tid);
    CP_COMMIT();

    for (int c = 0; c < nchunk; ++c) {
        if (c + 1 < nchunk) {
            gemm_load_chunk(sm0 + ((c + 1) & 1) * STAGEB, Ah, Al, Bh, Bl,
                            row0, col0, (c + 1) * 32, Kdim, tid);
            CP_COMMIT();
            CP_WAIT(1);
        } else {
            CP_WAIT(0);
        }
        __syncthreads();

        uint32_t sb = sm0 + (c & 1) * STAGEB;
#pragma unroll
        for (int ks = 0; ks < 2; ++ks) {
            const int kb = ks * 16;
            uint32_t bh[2][4], bl[2][4];
#pragma unroll
            for (int nt2 = 0; nt2 < 2; ++nt2) {
                uint32_t ba = sb + 2 * TILEB +
                    (uint32_t)((n0w + nt2 * 16 + fr) * GSTR + kb + fc) * 2;
                ldm_x4(bh[nt2], ba);
                ldm_x4(bl[nt2], ba + TILEB);
            }
#pragma unroll
            for (int mt = 0; mt < 4; ++mt) {
                uint32_t aa = sb +
                    (uint32_t)((m0w + mt * 16 + fr) * GSTR + kb + fc) * 2;
                uint32_t ah[4], al[4];
                ldm_x4(ah, aa);
                ldm_x4(al, aa + TILEB);
#pragma unroll
                for (int nt = 0; nt < 4; ++nt) {
                    uint32_t b0h = bh[nt >> 1][nt & 1];
                    uint32_t b1h = bh[nt >> 1][2 + (nt & 1)];
                    uint32_t b0l = bl[nt >> 1][nt & 1];
                    uint32_t b1l = bl[nt >> 1][2 + (nt & 1)];
                    mma_bf16(acc[mt][nt], ah, b0h, b1h);
                    mma_bf16(acc[mt][nt], ah, b0l, b1l);
                    mma_bf16(acc[mt][nt], al, b0h, b1h);
                }
            }
        }
        __syncthreads();
    }

    // epilogue: c0,c1 -> (row, col..col+1), c2,c3 -> (row+8, ...)
#pragma unroll
    for (int mt = 0; mt < 4; ++mt) {
#pragma unroll
        for (int nt = 0; nt < 4; ++nt) {
            int r  = row0 + m0w + mt * 16 + (lane >> 2);
            int cc = col0 + n0w + nt * 8 + (lane & 3) * 2;
            float2 v0; v0.x = acc[mt][nt][0]; v0.y = acc[mt][nt][1];
            float2 v1; v1.x = acc[mt][nt][2]; v1.y = acc[mt][nt][3];
            *(float2*)&C[(size_t)r * Ndim + cc] = v0;
            *(float2*)&C[(size_t)(r + 8) * Ndim + cc] = v1;
        }
    }
}

// ------------- RoPE (q,k) + transpose to [B,H,S,HD]; V transpose -----------
__global__ __launch_bounds__(256) void rope_transpose_kernel(
    const float* __restrict__ qlin, const float* __restrict__ klin,
    const float* __restrict__ vlin,
    const float* __restrict__ cosT, const float* __restrict__ sinT,
    float* __restrict__ Q, float* __restrict__ K, float* __restrict__ V)
{
    int idx = blockIdx.x * blockDim.x + threadIdx.x;
    const int HDH = HD / 2;
    int d2 = idx % HDH;
    int h  = (idx / HDH) % NH;
    int s  = (idx / (HDH * NH)) % SEQ;
    int b  = idx / (HDH * NH * SEQ);

    size_t m   = (size_t)b * SEQ + s;
    size_t src = m * DIM + h * HD + 2 * d2;
    float c  = cosT[s * HDH + d2];
    float sn = sinT[s * HDH + d2];

    size_t dst = (((size_t)(b * NH + h) * SEQ + s) * HD) + 2 * d2;

    float q0 = qlin[src], q1 = qlin[src + 1];
    Q[dst]     = q0 * c - q1 * sn;
    Q[dst + 1] = q0 * sn + q1 * c;

    float k0 = klin[src], k1 = klin[src + 1];
    K[dst]     = k0 * c - k1 * sn;
    K[dst + 1] = k0 * sn + k1 * c;

    V[dst]     = vlin[src];
    V[dst + 1] = vlin[src + 1];
}

// ---------------- Flash attention (causal, fp32) ---------------------------
#define BQ  64
#define BKV 64
#define QSTR (HD + 1)     // 129
#define PSTR (BKV + 1)    // 65
#define FLASH_SMEM_FLOATS (3 * BQ * QSTR + BQ * PSTR)
#define FLASH_SMEM_BYTES  (FLASH_SMEM_FLOATS * 4)

__global__ __launch_bounds__(256) void flash_attn_kernel(
    const float* __restrict__ Q, const float* __restrict__ K,
    const float* __restrict__ V, float* __restrict__ Out)
{
    extern __shared__ float sm[];
    float* Qs = sm;
    float* Ks = Qs + BQ * QSTR;
    float* Vs = Ks + BKV * QSTR;
    float* Ps = Vs + BKV * QSTR;

    const int bh = blockIdx.x;
    const int qt = blockIdx.y;
    const int t  = threadIdx.x;
    const int tx = t & 15;
    const int ty = t >> 4;

    const float scale = 0.08838834764831845f;

    const float* Qb = Q + ((size_t)bh * SEQ + (size_t)qt * BQ) * HD;
#pragma unroll
    for (int i = 0; i < (BQ * HD) / 256; i++) {
        int idx = t + i * 256;
        Qs[(idx >> 7) * QSTR + (idx & 127)] = Qb[idx];
    }

    float m_i[4], l_i[4], o[4][8];
#pragma unroll
    for (int i = 0; i < 4; i++) {
        m_i[i] = -INFINITY; l_i[i] = 0.f;
#pragma unroll
        for (int j = 0; j < 8; j++) o[i][j] = 0.f;
    }
    __syncthreads();

    for (int kt = 0; kt <= qt; kt++) {
        const float* Kb = K + ((size_t)bh * SEQ + (size_t)kt * BKV) * HD;
        const float* Vb = V + ((size_t)bh * SEQ + (size_t)kt * BKV) * HD;
#pragma unroll
        for (int i = 0; i < (BKV * HD) / 256; i++) {
            int idx = t + i * 256;
            int r = idx >> 7, c = idx & 127;
            Ks[r * QSTR + c] = Kb[idx];
            Vs[r * QSTR + c] = Vb[idx];
        }
        __syncthreads();

        float sc[4][4];
#pragma unroll
        for (int i = 0; i < 4; i++)
#pragma unroll
            for (int j = 0; j < 4; j++) sc[i][j] = 0.f;

        for (int kk = 0; kk < HD; kk++) {
            float a[4], b[4];
#pragma unroll
            for (int i = 0; i < 4; i++) a[i] = Qs[(ty * 4 + i) * QSTR + kk];
#pragma unroll
            for (int j = 0; j < 4; j++) b[j] = Ks[(tx * 4 + j) * QSTR + kk];
#pragma unroll
            for (int i = 0; i < 4; i++)
#pragma unroll
                for (int j = 0; j < 4; j++)
                    sc[i][j] = fmaf(a[i], b[j], sc[i][j]);
        }

        if (kt == qt) {
#pragma unroll
            for (int i = 0; i < 4; i++) {
                int rg = ty * 4 + i;
#pragma unroll
                for (int j = 0; j < 4; j++) {
                    int cg = tx * 4 + j;
                    sc[i][j] = (cg > rg) ? -INFINITY : sc[i][j] * scale;
                }
            }
        } else {
#pragma unroll
            for (int i = 0; i < 4; i++)
#pragma unroll
                for (int j = 0; j < 4; j++) sc[i][j] *= scale;
        }

#pragma unroll
        for (int i = 0; i < 4; i++) {
            float mloc = fmaxf(fmaxf(sc[i][0], sc[i][1]), fmaxf(sc[i][2], sc[i][3]));
#pragma unroll
            for (int off = 1; off < 16; off <<= 1)
                mloc = fmaxf(mloc, __shfl_xor_sync(0xffffffffu, mloc, off));

            float m_new = fmaxf(m_i[i], mloc);
            float alpha = __expf(m_i[i] - m_new);

            float p[4], rs = 0.f;
#pragma unroll
            for (int j = 0; j < 4; j++) {
                p[j] = __expf(sc[i][j] - m_new);
                rs += p[j];
            }
#pragma unroll
            for (int off = 1; off < 16; off <<= 1)
                rs += __shfl_xor_sync(0xffffffffu, rs, off);

            l_i[i] = l_i[i] * alpha + rs;
            m_i[i] = m_new;
#pragma unroll
            for (int j = 0; j < 8; j++) o[i][j] *= alpha;
#pragma unroll
            for (int j = 0; j < 4; j++)
                Ps[(ty * 4 + i) * PSTR + tx * 4 + j] = p[j];
        }
        __syncthreads();

        for (int c = 0; c < BKV; c++) {
            float pv[4], vv[8];
#pragma unroll
            for (int i = 0; i < 4; i++) pv[i] = Ps[(ty * 4 + i) * PSTR + c];
#pragma unroll
            for (int j = 0; j < 8; j++) vv[j] = Vs[c * QSTR + tx * 8 + j];
#pragma unroll
            for (int i = 0; i < 4; i++)
#pragma unroll
                for (int j = 0; j < 8; j++)
                    o[i][j] = fmaf(pv[i], vv[j], o[i][j]);
        }
        __syncthreads();
    }

    const int b = bh / NH, h = bh % NH;
#pragma unroll
    for (int i = 0; i < 4; i++) {
        int s = qt * BQ + ty * 4 + i;
        float inv_l = 1.0f / l_i[i];
        size_t base = ((size_t)(b * SEQ + s)) * DIM + h * HD + tx * 8;
#pragma unroll
        for (int j = 0; j < 8; j++)
            g_attn[base + j] = o[i][j] * inv_l;
    }
    (void)Out;
}

// ---------------------------------------------------------------------------
extern "C" void kernel_launch(void* const* d_in, const int* in_sizes, int n_in,
                              void* d_out, int out_size)
{
    const float* x    = (const float*)d_in[0];
    const float* wq   = (const float*)d_in[1];
    const float* wk   = (const float*)d_in[2];
    const float* wv   = (const float*)d_in[3];
    const float* wo   = (const float*)d_in[4];
    const float* fcos = (const float*)d_in[5];
    const float* fsin = (const float*)d_in[6];
    float* out = (float*)d_out;

    float *qlin, *klin, *vlin, *Qp, *Kp, *Vp, *attn;
    cudaGetSymbolAddress((void**)&qlin, g_qlin);
    cudaGetSymbolAddress((void**)&klin, g_klin);
    cudaGetSymbolAddress((void**)&vlin, g_vlin);
    cudaGetSymbolAddress((void**)&Qp,   g_Q);
    cudaGetSymbolAddress((void**)&Kp,   g_K);
    cudaGetSymbolAddress((void**)&Vp,   g_V);
    cudaGetSymbolAddress((void**)&attn, g_attn);

    __nv_bfloat16 *xh, *xl, *wqh, *wql, *wkh, *wkl, *wvh, *wvl, *woh, *wol, *ah, *al;
    cudaGetSymbolAddress((void**)&xh,  g_xh);
    cudaGetSymbolAddress((void**)&xl,  g_xl);
    cudaGetSymbolAddress((void**)&wqh, g_wqh);
    cudaGetSymbolAddress((void**)&wql, g_wql);
    cudaGetSymbolAddress((void**)&wkh, g_wkh);
    cudaGetSymbolAddress((void**)&wkl, g_wkl);
    cudaGetSymbolAddress((void**)&wvh, g_wvh);
    cudaGetSymbolAddress((void**)&wvl, g_wvl);
    cudaGetSymbolAddress((void**)&woh, g_woh);
    cudaGetSymbolAddress((void**)&wol, g_wol);
    cudaGetSymbolAddress((void**)&ah,  g_ah);
    cudaGetSymbolAddress((void**)&al,  g_al);

    cudaFuncSetAttribute(flash_attn_kernel,
                         cudaFuncAttributeMaxDynamicSharedMemorySize,
                         FLASH_SMEM_BYTES);
    cudaFuncSetAttribute(gemm_mma_kernel,
                         cudaFuncAttributeMaxDynamicSharedMemorySize,
                         GEMM_SMEM);

    // split inputs to bf16 hi/lo
    const int nx4 = (MROWS * DIM) / 4;
    const int nw4 = (DIM * DIM) / 4;
    split_kernel<<<(nx4 + 255) / 256, 256>>>((const float4*)x,
        (__nv_bfloat162*)xh, (__nv_bfloat162*)xl, nx4);
    split_kernel<<<(nw4 + 255) / 256, 256>>>((const float4*)wq,
        (__nv_bfloat162*)wqh, (__nv_bfloat162*)wql, nw4);
    split_kernel<<<(nw4 + 255) / 256, 256>>>((const float4*)wk,
        (__nv_bfloat162*)wkh, (__nv_bfloat162*)wkl, nw4);
    split_kernel<<<(nw4 + 255) / 256, 256>>>((const float4*)wv,
        (__nv_bfloat162*)wvh, (__nv_bfloat162*)wvl, nw4);
    split_kernel<<<(nw4 + 255) / 256, 256>>>((const float4*)wo,
        (__nv_bfloat162*)woh, (__nv_bfloat162*)wol, nw4);

    // QKV projections on tensor cores (mma.sync path)
    dim3 gGrid(DIM / 128, MROWS / 128);
    gemm_mma_kernel<<<gGrid, 256, GEMM_SMEM>>>(xh, xl, wqh, wql, qlin, MROWS, DIM, DIM);
    gemm_mma_kernel<<<gGrid, 256, GEMM_SMEM>>>(xh, xl, wkh, wkl, klin, MROWS, DIM, DIM);
    gemm_mma_kernel<<<gGrid, 256, GEMM_SMEM>>>(xh, xl, wvh, wvl, vlin, MROWS, DIM, DIM);

    int ropeElems = BSZ * SEQ * NH * (HD / 2);
    rope_transpose_kernel<<<ropeElems / 256, 256>>>(qlin, klin, vlin,
                                                    fcos, fsin, Qp, Kp, Vp);

    flash_attn_kernel<<<dim3(BSZ * NH, SEQ / BQ), 256, FLASH_SMEM_BYTES>>>(
        Qp, Kp, Vp, attn);

    // output projection
    split_kernel<<<(nx4 + 255) / 256, 256>>>((const float4*)attn,
        (__nv_bfloat162*)ah, (__nv_bfloat162*)al, nx4);
    gemm_mma_kernel<<<gGrid, 256, GEMM_SMEM>>>(ah, al, woh, wol, out, MROWS, DIM, DIM);
}

// round 5
// speedup vs baseline: 3.0760x; 1.8006x over previous
#include <cuda_runtime.h>
#include <cuda_bf16.h>
#include <math.h>
#include <stdint.h>

#define BSZ 2
#define SEQ 2048
#define DIM 2048
#define NH  16
#define HD  128
#define MROWS (BSZ*SEQ)          // 4096

// ---------------- scratch (static device globals; no allocation) -----------
__device__ float g_qlin[(size_t)MROWS * DIM];
__device__ float g_klin[(size_t)MROWS * DIM];
__device__ float g_vlin[(size_t)MROWS * DIM];

// bf16 split-precision operands
__device__ __nv_bfloat16 g_xh[(size_t)MROWS * DIM];
__device__ __nv_bfloat16 g_xl[(size_t)MROWS * DIM];
__device__ __nv_bfloat16 g_wqh[(size_t)DIM * DIM];
__device__ __nv_bfloat16 g_wql[(size_t)DIM * DIM];
__device__ __nv_bfloat16 g_wkh[(size_t)DIM * DIM];
__device__ __nv_bfloat16 g_wkl[(size_t)DIM * DIM];
__device__ __nv_bfloat16 g_wvh[(size_t)DIM * DIM];
__device__ __nv_bfloat16 g_wvl[(size_t)DIM * DIM];
__device__ __nv_bfloat16 g_woh[(size_t)DIM * DIM];
__device__ __nv_bfloat16 g_wol[(size_t)DIM * DIM];
__device__ __nv_bfloat16 g_ah[(size_t)MROWS * DIM];
__device__ __nv_bfloat16 g_al[(size_t)MROWS * DIM];

// per-head bf16 hi/lo Q,K,V  [B*NH, SEQ, HD]
#define HELEMS ((size_t)BSZ * NH * SEQ * HD)
__device__ __nv_bfloat16 g_Qh[HELEMS];
__device__ __nv_bfloat16 g_Ql[HELEMS];
__device__ __nv_bfloat16 g_Kh[HELEMS];
__device__ __nv_bfloat16 g_Kl[HELEMS];
__device__ __nv_bfloat16 g_Vh[HELEMS];
__device__ __nv_bfloat16 g_Vl[HELEMS];

// ======================= helpers ==========================================
__device__ __forceinline__ uint32_t smem_u32(const void* p) {
    uint32_t a;
    asm("{ .reg .u64 t; cvta.to.shared.u64 t, %1; cvt.u32.u64 %0, t; }"
        : "=r"(a) : "l"(p));
    return a;
}
__device__ __forceinline__ void cp16(uint32_t saddr, const void* g) {
    asm volatile("cp.async.ca.shared.global [%0], [%1], 16;"
                 :: "r"(saddr), "l"(g));
}
#define CP_COMMIT() asm volatile("cp.async.commit_group;" ::: "memory")
#define CP_WAIT(n)  asm volatile("cp.async.wait_group %0;" :: "n"(n) : "memory")

__device__ __forceinline__ void ldm_x4(uint32_t* d, uint32_t addr) {
    asm volatile("ldmatrix.sync.aligned.m8n8.x4.shared.b16 {%0,%1,%2,%3}, [%4];"
                 : "=r"(d[0]), "=r"(d[1]), "=r"(d[2]), "=r"(d[3]) : "r"(addr));
}
__device__ __forceinline__ void ldm_x4t(uint32_t* d, uint32_t addr) {
    asm volatile("ldmatrix.sync.aligned.m8n8.x4.trans.shared.b16 {%0,%1,%2,%3}, [%4];"
                 : "=r"(d[0]), "=r"(d[1]), "=r"(d[2]), "=r"(d[3]) : "r"(addr));
}
__device__ __forceinline__ void mma_bf16(float* c, const uint32_t* a,
                                         uint32_t b0, uint32_t b1) {
    asm volatile(
        "mma.sync.aligned.m16n8k16.row.col.f32.bf16.bf16.f32 "
        "{%0,%1,%2,%3}, {%4,%5,%6,%7}, {%8,%9}, {%0,%1,%2,%3};"
        : "+f"(c[0]), "+f"(c[1]), "+f"(c[2]), "+f"(c[3])
        : "r"(a[0]), "r"(a[1]), "r"(a[2]), "r"(a[3]), "r"(b0), "r"(b1));
}
// pack {lo, hi} floats -> bf16x2 (lo in low half)
__device__ __forceinline__ uint32_t pk2(float lo, float hi) {
    uint32_t r;
    asm("cvt.rn.bf16x2.f32 %0, %1, %2;" : "=r"(r) : "f"(hi), "f"(lo));
    return r;
}
__device__ __forceinline__ float bfr(float v) {   // bf16 round-trip
    return __bfloat162float(__float2bfloat16(v));
}

// =================== split fp32 -> (hi, lo) bf16 ===========================
__global__ __launch_bounds__(256) void split_kernel(
    const float4* __restrict__ in, __nv_bfloat162* __restrict__ hi,
    __nv_bfloat162* __restrict__ lo, int n4)
{
    int i = blockIdx.x * blockDim.x + threadIdx.x;
    if (i >= n4) return;
    float4 v = in[i];
    float h0 = bfr(v.x), h1 = bfr(v.y), h2 = bfr(v.z), h3 = bfr(v.w);
    ((uint32_t*)hi)[2 * i]     = pk2(v.x, v.y);
    ((uint32_t*)hi)[2 * i + 1] = pk2(v.z, v.w);
    ((uint32_t*)lo)[2 * i]     = pk2(v.x - h0, v.y - h1);
    ((uint32_t*)lo)[2 * i + 1] = pk2(v.z - h2, v.w - h3);
}

// =============== mma.sync NT GEMM (split bf16, fp32 accum) =================
#define GSTR 40                        // smem row stride in halves
#define TILEB (128 * GSTR * 2)         // 10240 bytes per operand tile
#define STAGEB (4 * TILEB)             // Ah,Al,Bh,Bl = 40960 bytes
#define GEMM_SMEM (2 * STAGEB)         // 81920 bytes

__device__ __forceinline__ void gemm_load_chunk(
    uint32_t sbase,
    const __nv_bfloat16* __restrict__ Ah, const __nv_bfloat16* __restrict__ Al,
    const __nv_bfloat16* __restrict__ Bh, const __nv_bfloat16* __restrict__ Bl,
    int row0, int col0, int k0, int Kdim, int tid)
{
#pragma unroll
    for (int i = 0; i < 2; ++i) {
        int v = tid + i * 256;
        int r = v >> 2, cv = v & 3;
        uint32_t soff = (uint32_t)(r * GSTR + cv * 8) * 2;
        size_t gA = (size_t)(row0 + r) * Kdim + k0 + cv * 8;
        size_t gB = (size_t)(col0 + r) * Kdim + k0 + cv * 8;
        cp16(sbase + soff,             Ah + gA);
        cp16(sbase + TILEB + soff,     Al + gA);
        cp16(sbase + 2 * TILEB + soff, Bh + gB);
        cp16(sbase + 3 * TILEB + soff, Bl + gB);
    }
}

__global__ __launch_bounds__(256) void gemm_mma_kernel(
    const __nv_bfloat16* __restrict__ Ah, const __nv_bfloat16* __restrict__ Al,
    const __nv_bfloat16* __restrict__ Bh, const __nv_bfloat16* __restrict__ Bl,
    float* __restrict__ C, int Mdim, int Ndim, int Kdim)
{
    extern __shared__ char smem[];
    uint32_t sm0 = smem_u32(smem);

    const int tid  = threadIdx.x;
    const int wid  = tid >> 5;
    const int lane = tid & 31;
    const int wr = wid >> 2, wc = wid & 3;
    const int m0w = wr * 64, n0w = wc * 32;
    const int row0 = blockIdx.y * 128;
    const int col0 = blockIdx.x * 128;

    const int g  = lane >> 3;
    const int fr = (g & 1) * 8 + (lane & 7);
    const int fc = (g >> 1) * 8;

    float acc[4][4][4];
#pragma unroll
    for (int a = 0; a < 4; a++)
#pragma unroll
        for (int b = 0; b < 4; b++)
#pragma unroll
            for (int d = 0; d < 4; d++) acc[a][b][d] = 0.f;

    const int nchunk = Kdim / 32;

    gemm_load_chunk(sm0, Ah, Al, Bh, Bl, row0, col0, 0, Kdim, tid);
    CP_COMMIT();

    for (int c = 0; c < nchunk; ++c) {
        if (c + 1 < nchunk) {
            gemm_load_chunk(sm0 + ((c + 1) & 1) * STAGEB, Ah, Al, Bh, Bl,
                            row0, col0, (c + 1) * 32, Kdim, tid);
            CP_COMMIT();
            CP_WAIT(1);
        } else {
            CP_WAIT(0);
        }
        __syncthreads();

        uint32_t sb = sm0 + (c & 1) * STAGEB;
#pragma unroll
        for (int ks = 0; ks < 2; ++ks) {
            const int kb = ks * 16;
            uint32_t bh[2][4], bl[2][4];
#pragma unroll
            for (int nt2 = 0; nt2 < 2; ++nt2) {
                uint32_t ba = sb + 2 * TILEB +
                    (uint32_t)((n0w + nt2 * 16 + fr) * GSTR + kb + fc) * 2;
                ldm_x4(bh[nt2], ba);
                ldm_x4(bl[nt2], ba + TILEB);
            }
#pragma unroll
            for (int mt = 0; mt < 4; ++mt) {
                uint32_t aa = sb +
                    (uint32_t)((m0w + mt * 16 + fr) * GSTR + kb + fc) * 2;
                uint32_t ah[4], al[4];
                ldm_x4(ah, aa);
                ldm_x4(al, aa + TILEB);
#pragma unroll
                for (int nt = 0; nt < 4; ++nt) {
                    uint32_t b0h = bh[nt >> 1][nt & 1];
                    uint32_t b1h = bh[nt >> 1][2 + (nt & 1)];
                    uint32_t b0l = bl[nt >> 1][nt & 1];
                    uint32_t b1l = bl[nt >> 1][2 + (nt & 1)];
                    mma_bf16(acc[mt][nt], ah, b0h, b1h);
                    mma_bf16(acc[mt][nt], ah, b0l, b1l);
                    mma_bf16(acc[mt][nt], al, b0h, b1h);
                }
            }
        }
        __syncthreads();
    }

#pragma unroll
    for (int mt = 0; mt < 4; ++mt) {
#pragma unroll
        for (int nt = 0; nt < 4; ++nt) {
            int r  = row0 + m0w + mt * 16 + (lane >> 2);
            int cc = col0 + n0w + nt * 8 + (lane & 3) * 2;
            float2 v0; v0.x = acc[mt][nt][0]; v0.y = acc[mt][nt][1];
            float2 v1; v1.x = acc[mt][nt][2]; v1.y = acc[mt][nt][3];
            *(float2*)&C[(size_t)r * Ndim + cc] = v0;
            *(float2*)&C[(size_t)(r + 8) * Ndim + cc] = v1;
        }
    }
}

// ------ RoPE + transpose to [B*H,S,HD] + split into hi/lo bf16 -------------
__global__ __launch_bounds__(256) void rope_split_kernel(
    const float* __restrict__ qlin, const float* __restrict__ klin,
    const float* __restrict__ vlin,
    const float* __restrict__ cosT, const float* __restrict__ sinT,
    uint32_t* __restrict__ Qh, uint32_t* __restrict__ Ql,
    uint32_t* __restrict__ Kh, uint32_t* __restrict__ Kl,
    uint32_t* __restrict__ Vh, uint32_t* __restrict__ Vl)
{
    int idx = blockIdx.x * blockDim.x + threadIdx.x;
    const int HDH = HD / 2;
    int d2 = idx % HDH;
    int h  = (idx / HDH) % NH;
    int s  = (idx / (HDH * NH)) % SEQ;
    int b  = idx / (HDH * NH * SEQ);

    size_t src = ((size_t)(b * SEQ + s)) * DIM + h * HD + 2 * d2;
    float c  = cosT[s * HDH + d2];
    float sn = sinT[s * HDH + d2];
    size_t dst = ((((size_t)(b * NH + h)) * SEQ + s) * HD + 2 * d2) >> 1;

    float q0 = qlin[src], q1 = qlin[src + 1];
    float k0 = klin[src], k1 = klin[src + 1];
    float v0 = vlin[src], v1 = vlin[src + 1];
    float qa = q0 * c - q1 * sn, qb = q0 * sn + q1 * c;
    float ka = k0 * c - k1 * sn, kb = k0 * sn + k1 * c;

    float qah = bfr(qa), qbh = bfr(qb);
    float kah = bfr(ka), kbh = bfr(kb);
    float vah = bfr(v0), vbh = bfr(v1);
    Qh[dst] = pk2(qa, qb); Ql[dst] = pk2(qa - qah, qb - qbh);
    Kh[dst] = pk2(ka, kb); Kl[dst] = pk2(ka - kah, kb - kbh);
    Vh[dst] = pk2(v0, v1); Vl[dst] = pk2(v0 - vah, v1 - vbh);
}

// ============= Flash attention via mma.sync (split bf16) ===================
// CTA: 128 q-rows, 8 warps x 16 rows. BKV=64. double-buffered K/V hi/lo.
#define FQS   272                  // smem row stride in BYTES (136 halves)
#define FB_QH 0
#define FB_QL 34816                // 128*272
#define FB_ST 69632
#define FSTG  69632                // 4 * 64*272
#define FB_KH 0
#define FB_KL 17408
#define FB_VH 34816
#define FB_VL 52224
#define FLASH_SMEM (FB_ST + 2 * FSTG)   // 208896

__global__ __launch_bounds__(256, 1) void flash_mma_kernel(
    const __nv_bfloat16* __restrict__ Qh, const __nv_bfloat16* __restrict__ Ql,
    const __nv_bfloat16* __restrict__ Kh, const __nv_bfloat16* __restrict__ Kl,
    const __nv_bfloat16* __restrict__ Vh, const __nv_bfloat16* __restrict__ Vl,
    uint32_t* __restrict__ outH, uint32_t* __restrict__ outL)
{
    extern __shared__ char smem[];
    uint32_t s0 = smem_u32(smem);
    const int bh  = blockIdx.x;
    const int qt  = (int)gridDim.y - 1 - (int)blockIdx.y;   // big tiles first
    const int tid = threadIdx.x, wid = tid >> 5, lane = tid & 31;
    const int m0w = wid * 16;
    const int gg  = lane >> 3;
    const int fr  = (gg & 1) * 8 + (lane & 7);
    const int fc  = (gg >> 1) * 8;
    const int q0  = qt * 128;
    const size_t hoff = (size_t)bh * SEQ * HD;
    const float scale = 0.08838834764831845f;   // 1/sqrt(128)

    // group 0: Q (hi+lo) + kv tile 0
    {
        const __nv_bfloat16* gq_h = Qh + hoff + (size_t)q0 * HD;
        const __nv_bfloat16* gq_l = Ql + hoff + (size_t)q0 * HD;
#pragma unroll
        for (int i = 0; i < 8; i++) {
            int v = tid + (i << 8); int r = v >> 4, c = v & 15;
            uint32_t so = (uint32_t)(r * FQS + c * 16);
            cp16(s0 + FB_QH + so, gq_h + r * HD + c * 8);
            cp16(s0 + FB_QL + so, gq_l + r * HD + c * 8);
        }
        uint32_t sb = s0 + FB_ST;
#pragma unroll
        for (int i = 0; i < 4; i++) {
            int v = tid + (i << 8); int r = v >> 4, c = v & 15;
            uint32_t so = (uint32_t)(r * FQS + c * 16);
            size_t go = hoff + r * HD + c * 8;
            cp16(sb + FB_KH + so, Kh + go);
            cp16(sb + FB_KL + so, Kl + go);
            cp16(sb + FB_VH + so, Vh + go);
            cp16(sb + FB_VL + so, Vl + go);
        }
    }
    CP_COMMIT();

    float O[16][4];
#pragma unroll
    for (int i = 0; i < 16; i++)
#pragma unroll
        for (int j = 0; j < 4; j++) O[i][j] = 0.f;
    float m0 = -1e30f, m1 = -1e30f, l0 = 0.f, l1 = 0.f;

    const int last  = 2 * qt + 1;
    const int r0g   = q0 + m0w + (lane >> 2);
    const int cbase = (lane & 3) * 2;

    for (int kt = 0; kt <= last; kt++) {
        const int stg = kt & 1;
        if (kt < last) {
            uint32_t sb = s0 + FB_ST + (stg ^ 1) * FSTG;
            size_t kvo = hoff + (size_t)(kt + 1) * 64 * HD;
#pragma unroll
            for (int i = 0; i < 4; i++) {
                int v = tid + (i << 8); int r = v >> 4, c = v & 15;
                uint32_t so = (uint32_t)(r * FQS + c * 16);
                size_t go = kvo + r * HD + c * 8;
                cp16(sb + FB_KH + so, Kh + go);
                cp16(sb + FB_KL + so, Kl + go);
                cp16(sb + FB_VH + so, Vh + go);
                cp16(sb + FB_VL + so, Vl + go);
            }
            CP_COMMIT();
            CP_WAIT(1);
        } else {
            CP_WAIT(0);
        }
        __syncthreads();

        uint32_t sb = s0 + FB_ST + stg * FSTG;

        // ---- S = Q K^T (3-pass split) ----
        float Sv[8][4];
#pragma unroll
        for (int i = 0; i < 8; i++)
#pragma unroll
            for (int j = 0; j < 4; j++) Sv[i][j] = 0.f;

#pragma unroll
        for (int kk = 0; kk < 8; kk++) {
            uint32_t qoff = (uint32_t)((m0w + fr) * FQS + (kk * 16 + fc) * 2);
            uint32_t ah[4], al[4];
            ldm_x4(ah, s0 + FB_QH + qoff);
            ldm_x4(al, s0 + FB_QL + qoff);
#pragma unroll
            for (int nt2 = 0; nt2 < 4; nt2++) {
                uint32_t koff = (uint32_t)((nt2 * 16 + fr) * FQS + (kk * 16 + fc) * 2);
                uint32_t bh4[4], bl4[4];
                ldm_x4(bh4, sb + FB_KH + koff);
                ldm_x4(bl4, sb + FB_KL + koff);
                mma_bf16(Sv[2 * nt2],     ah, bh4[0], bh4[2]);
                mma_bf16(Sv[2 * nt2 + 1], ah, bh4[1], bh4[3]);
                mma_bf16(Sv[2 * nt2],     ah, bl4[0], bl4[2]);
                mma_bf16(Sv[2 * nt2 + 1], ah, bl4[1], bl4[3]);
                mma_bf16(Sv[2 * nt2],     al, bh4[0], bh4[2]);
                mma_bf16(Sv[2 * nt2 + 1], al, bh4[1], bh4[3]);
            }
        }

        // ---- scale + causal mask ----
        if (kt >= 2 * qt) {
#pragma unroll
            for (int nt = 0; nt < 8; nt++) {
                int c0 = kt * 64 + nt * 8 + cbase;
                Sv[nt][0] = (c0     > r0g)     ? -1e30f : Sv[nt][0] * scale;
                Sv[nt][1] = (c0 + 1 > r0g)     ? -1e30f : Sv[nt][1] * scale;
                Sv[nt][2] = (c0     > r0g + 8) ? -1e30f : Sv[nt][2] * scale;
                Sv[nt][3] = (c0 + 1 > r0g + 8) ? -1e30f : Sv[nt][3] * scale;
            }
        } else {
#pragma unroll
            for (int nt = 0; nt < 8; nt++)
#pragma unroll
                for (int j = 0; j < 4; j++) Sv[nt][j] *= scale;
        }

        // ---- online softmax (rows r0g and r0g+8, 4 lanes each) ----
        float mx0 = -1e30f, mx1 = -1e30f;
#pragma unroll
        for (int nt = 0; nt < 8; nt++) {
            mx0 = fmaxf(mx0, fmaxf(Sv[nt][0], Sv[nt][1]));
            mx1 = fmaxf(mx1, fmaxf(Sv[nt][2], Sv[nt][3]));
        }
        mx0 = fmaxf(mx0, __shfl_xor_sync(0xffffffffu, mx0, 1));
        mx0 = fmaxf(mx0, __shfl_xor_sync(0xffffffffu, mx0, 2));
        mx1 = fmaxf(mx1, __shfl_xor_sync(0xffffffffu, mx1, 1));
        mx1 = fmaxf(mx1, __shfl_xor_sync(0xffffffffu, mx1, 2));

        float mn0 = fmaxf(m0, mx0), mn1 = fmaxf(m1, mx1);
        float al0 = __expf(m0 - mn0), al1 = __expf(m1 - mn1);
        float sum0 = 0.f, sum1 = 0.f;
#pragma unroll
        for (int nt = 0; nt < 8; nt++) {
            Sv[nt][0] = __expf(Sv[nt][0] - mn0); sum0 += Sv[nt][0];
            Sv[nt][1] = __expf(Sv[nt][1] - mn0); sum0 += Sv[nt][1];
            Sv[nt][2] = __expf(Sv[nt][2] - mn1); sum1 += Sv[nt][2];
            Sv[nt][3] = __expf(Sv[nt][3] - mn1); sum1 += Sv[nt][3];
        }
        sum0 += __shfl_xor_sync(0xffffffffu, sum0, 1);
        sum0 += __shfl_xor_sync(0xffffffffu, sum0, 2);
        sum1 += __shfl_xor_sync(0xffffffffu, sum1, 1);
        sum1 += __shfl_xor_sync(0xffffffffu, sum1, 2);
        l0 = l0 * al0 + sum0; l1 = l1 * al1 + sum1;
        m0 = mn0; m1 = mn1;
#pragma unroll
        for (int nt = 0; nt < 16; nt++) {
            O[nt][0] *= al0; O[nt][1] *= al0;
            O[nt][2] *= al1; O[nt][3] *= al1;
        }

        // ---- O += P V (3-pass split); P frags built from registers ----
#pragma unroll
        for (int kk = 0; kk < 4; kk++) {
            uint32_t pah[4], pal[4];
            float x0 = Sv[2 * kk][0],     x1 = Sv[2 * kk][1];
            float x2 = Sv[2 * kk][2],     x3 = Sv[2 * kk][3];
            float y0 = Sv[2 * kk + 1][0], y1 = Sv[2 * kk + 1][1];
            float y2 = Sv[2 * kk + 1][2], y3 = Sv[2 * kk + 1][3];
            pah[0] = pk2(x0, x1); pah[1] = pk2(x2, x3);
            pah[2] = pk2(y0, y1); pah[3] = pk2(y2, y3);
            pal[0] = pk2(x0 - bfr(x0), x1 - bfr(x1));
            pal[1] = pk2(x2 - bfr(x2), x3 - bfr(x3));
            pal[2] = pk2(y0 - bfr(y0), y1 - bfr(y1));
            pal[3] = pk2(y2 - bfr(y2), y3 - bfr(y3));
#pragma unroll
            for (int j = 0; j < 8; j++) {
                uint32_t vo = (uint32_t)((kk * 16 + fr) * FQS + (j * 16 + fc) * 2);
                uint32_t vh4[4], vl4[4];
                ldm_x4t(vh4, sb + FB_VH + vo);
                ldm_x4t(vl4, sb + FB_VL + vo);
                mma_bf16(O[2 * j],     pah, vh4[0], vh4[1]);
                mma_bf16(O[2 * j + 1], pah, vh4[2], vh4[3]);
                mma_bf16(O[2 * j],     pah, vl4[0], vl4[1]);
                mma_bf16(O[2 * j + 1], pah, vl4[2], vl4[3]);
                mma_bf16(O[2 * j],     pal, vh4[0], vh4[1]);
                mma_bf16(O[2 * j + 1], pal, vh4[2], vh4[3]);
            }
        }
        __syncthreads();
    }

    // ---- epilogue: normalize, split hi/lo, store to [B,S,DIM] ----
    float inv0 = 1.f / l0, inv1 = 1.f / l1;
    const int b = bh >> 4, h = bh & 15;
    const int s_row = q0 + m0w + (lane >> 2);
#pragma unroll
    for (int nt = 0; nt < 16; nt++) {
        int col = h * HD + nt * 8 + cbase;
        {
            float v0 = O[nt][0] * inv0, v1 = O[nt][1] * inv0;
            size_t o = (((size_t)(b * SEQ + s_row)) * DIM + col) >> 1;
            outH[o] = pk2(v0, v1);
            outL[o] = pk2(v0 - bfr(v0), v1 - bfr(v1));
        }
        {
            float v0 = O[nt][2] * inv1, v1 = O[nt][3] * inv1;
            size_t o = (((size_t)(b * SEQ + s_row + 8)) * DIM + col) >> 1;
            outH[o] = pk2(v0, v1);
            outL[o] = pk2(v0 - bfr(v0), v1 - bfr(v1));
        }
    }
}

// ---------------------------------------------------------------------------
extern "C" void kernel_launch(void* const* d_in, const int* in_sizes, int n_in,
                              void* d_out, int out_size)
{
    const float* x    = (const float*)d_in[0];
    const float* wq   = (const float*)d_in[1];
    const float* wk   = (const float*)d_in[2];
    const float* wv   = (const float*)d_in[3];
    const float* wo   = (const float*)d_in[4];
    const float* fcos = (const float*)d_in[5];
    const float* fsin = (const float*)d_in[6];
    float* out = (float*)d_out;

    float *qlin, *klin, *vlin;
    cudaGetSymbolAddress((void**)&qlin, g_qlin);
    cudaGetSymbolAddress((void**)&klin, g_klin);
    cudaGetSymbolAddress((void**)&vlin, g_vlin);

    __nv_bfloat16 *xh, *xl, *wqh, *wql, *wkh, *wkl, *wvh, *wvl, *woh, *wol, *ah, *al;
    cudaGetSymbolAddress((void**)&xh,  g_xh);
    cudaGetSymbolAddress((void**)&xl,  g_xl);
    cudaGetSymbolAddress((void**)&wqh, g_wqh);
    cudaGetSymbolAddress((void**)&wql, g_wql);
    cudaGetSymbolAddress((void**)&wkh, g_wkh);
    cudaGetSymbolAddress((void**)&wkl, g_wkl);
    cudaGetSymbolAddress((void**)&wvh, g_wvh);
    cudaGetSymbolAddress((void**)&wvl, g_wvl);
    cudaGetSymbolAddress((void**)&woh, g_woh);
    cudaGetSymbolAddress((void**)&wol, g_wol);
    cudaGetSymbolAddress((void**)&ah,  g_ah);
    cudaGetSymbolAddress((void**)&al,  g_al);

    __nv_bfloat16 *Qh, *Ql, *Kh, *Kl, *Vh, *Vl;
    cudaGetSymbolAddress((void**)&Qh, g_Qh);
    cudaGetSymbolAddress((void**)&Ql, g_Ql);
    cudaGetSymbolAddress((void**)&Kh, g_Kh);
    cudaGetSymbolAddress((void**)&Kl, g_Kl);
    cudaGetSymbolAddress((void**)&Vh, g_Vh);
    cudaGetSymbolAddress((void**)&Vl, g_Vl);

    cudaFuncSetAttribute(gemm_mma_kernel,
                         cudaFuncAttributeMaxDynamicSharedMemorySize, GEMM_SMEM);
    cudaFuncSetAttribute(flash_mma_kernel,
                         cudaFuncAttributeMaxDynamicSharedMemorySize, FLASH_SMEM);

    const int nx4 = (MROWS * DIM) / 4;
    const int nw4 = (DIM * DIM) / 4;
    split_kernel<<<(nx4 + 255) / 256, 256>>>((const float4*)x,
        (__nv_bfloat162*)xh, (__nv_bfloat162*)xl, nx4);
    split_kernel<<<(nw4 + 255) / 256, 256>>>((const float4*)wq,
        (__nv_bfloat162*)wqh, (__nv_bfloat162*)wql, nw4);
    split_kernel<<<(nw4 + 255) / 256, 256>>>((const float4*)wk,
        (__nv_bfloat162*)wkh, (__nv_bfloat162*)wkl, nw4);
    split_kernel<<<(nw4 + 255) / 256, 256>>>((const float4*)wv,
        (__nv_bfloat162*)wvh, (__nv_bfloat162*)wvl, nw4);
    split_kernel<<<(nw4 + 255) / 256, 256>>>((const float4*)wo,
        (__nv_bfloat162*)woh, (__nv_bfloat162*)wol, nw4);

    dim3 gGrid(DIM / 128, MROWS / 128);
    gemm_mma_kernel<<<gGrid, 256, GEMM_SMEM>>>(xh, xl, wqh, wql, qlin, MROWS, DIM, DIM);
    gemm_mma_kernel<<<gGrid, 256, GEMM_SMEM>>>(xh, xl, wkh, wkl, klin, MROWS, DIM, DIM);
    gemm_mma_kernel<<<gGrid, 256, GEMM_SMEM>>>(xh, xl, wvh, wvl, vlin, MROWS, DIM, DIM);

    int ropeElems = BSZ * SEQ * NH * (HD / 2);
    rope_split_kernel<<<ropeElems / 256, 256>>>(qlin, klin, vlin, fcos, fsin,
        (uint32_t*)Qh, (uint32_t*)Ql, (uint32_t*)Kh, (uint32_t*)Kl,
        (uint32_t*)Vh, (uint32_t*)Vl);

    flash_mma_kernel<<<dim3(BSZ * NH, SEQ / 128), 256, FLASH_SMEM>>>(
        Qh, Ql, Kh, Kl, Vh, Vl, (uint32_t*)ah, (uint32_t*)al);

    gemm_mma_kernel<<<gGrid, 256, GEMM_SMEM>>>(ah, al, woh, wol, out, MROWS, DIM, DIM);
}

// round 6
// speedup vs baseline: 3.6432x; 1.1844x over previous
#include <cuda_runtime.h>
#include <cuda_fp16.h>
#include <math.h>
#include <stdint.h>

#define BSZ 2
#define SEQ 2048
#define DIM 2048
#define NH  16
#define HD  128
#define MROWS (BSZ*SEQ)          // 4096

// ---------------- scratch (static device globals; no allocation) -----------
__device__ float g_qlin[(size_t)MROWS * DIM];
__device__ float g_klin[(size_t)MROWS * DIM];
__device__ float g_vlin[(size_t)MROWS * DIM];

// fp16 split-precision operands
__device__ __half g_xh[(size_t)MROWS * DIM];
__device__ __half g_xl[(size_t)MROWS * DIM];
__device__ __half g_wqh[(size_t)DIM * DIM];
__device__ __half g_wql[(size_t)DIM * DIM];
__device__ __half g_wkh[(size_t)DIM * DIM];
__device__ __half g_wkl[(size_t)DIM * DIM];
__device__ __half g_wvh[(size_t)DIM * DIM];
__device__ __half g_wvl[(size_t)DIM * DIM];
__device__ __half g_woh[(size_t)DIM * DIM];
__device__ __half g_wol[(size_t)DIM * DIM];
__device__ __half g_ah[(size_t)MROWS * DIM];     // attention out (hi only)

// per-head fp16 hi/lo Q,K,V  [B*NH, SEQ, HD]
#define HELEMS ((size_t)BSZ * NH * SEQ * HD)
__device__ __half g_Qh[HELEMS];
__device__ __half g_Ql[HELEMS];
__device__ __half g_Kh[HELEMS];
__device__ __half g_Kl[HELEMS];
__device__ __half g_Vh[HELEMS];
__device__ __half g_Vl[HELEMS];

// ======================= helpers ==========================================
__device__ __forceinline__ uint32_t smem_u32(const void* p) {
    uint32_t a;
    asm("{ .reg .u64 t; cvta.to.shared.u64 t, %1; cvt.u32.u64 %0, t; }"
        : "=r"(a) : "l"(p));
    return a;
}
__device__ __forceinline__ void cp16(uint32_t saddr, const void* g) {
    asm volatile("cp.async.ca.shared.global [%0], [%1], 16;"
                 :: "r"(saddr), "l"(g));
}
#define CP_COMMIT() asm volatile("cp.async.commit_group;" ::: "memory")
#define CP_WAIT(n)  asm volatile("cp.async.wait_group %0;" :: "n"(n) : "memory")

__device__ __forceinline__ void ldm_x4(uint32_t* d, uint32_t addr) {
    asm volatile("ldmatrix.sync.aligned.m8n8.x4.shared.b16 {%0,%1,%2,%3}, [%4];"
                 : "=r"(d[0]), "=r"(d[1]), "=r"(d[2]), "=r"(d[3]) : "r"(addr));
}
__device__ __forceinline__ void ldm_x4t(uint32_t* d, uint32_t addr) {
    asm volatile("ldmatrix.sync.aligned.m8n8.x4.trans.shared.b16 {%0,%1,%2,%3}, [%4];"
                 : "=r"(d[0]), "=r"(d[1]), "=r"(d[2]), "=r"(d[3]) : "r"(addr));
}
__device__ __forceinline__ void mma_f16(float* c, const uint32_t* a,
                                        uint32_t b0, uint32_t b1) {
    asm volatile(
        "mma.sync.aligned.m16n8k16.row.col.f32.f16.f16.f32 "
        "{%0,%1,%2,%3}, {%4,%5,%6,%7}, {%8,%9}, {%0,%1,%2,%3};"
        : "+f"(c[0]), "+f"(c[1]), "+f"(c[2]), "+f"(c[3])
        : "r"(a[0]), "r"(a[1]), "r"(a[2]), "r"(a[3]), "r"(b0), "r"(b1));
}
// pack {lo, hi} floats -> f16x2 (lo in low half)
__device__ __forceinline__ uint32_t pk2(float lo, float hi) {
    uint32_t r;
    asm("cvt.rn.f16x2.f32 %0, %1, %2;" : "=r"(r) : "f"(hi), "f"(lo));
    return r;
}
__device__ __forceinline__ float hrt(float v) {   // fp16 round-trip
    return __half2float(__float2half_rn(v));
}

// =================== split fp32 -> (hi, lo) fp16 ===========================
__global__ __launch_bounds__(256) void split_kernel(
    const float4* __restrict__ in, uint32_t* __restrict__ hi,
    uint32_t* __restrict__ lo, int n4)
{
    int i = blockIdx.x * blockDim.x + threadIdx.x;
    if (i >= n4) return;
    float4 v = in[i];
    float h0 = hrt(v.x), h1 = hrt(v.y), h2 = hrt(v.z), h3 = hrt(v.w);
    hi[2 * i]     = pk2(v.x, v.y);
    hi[2 * i + 1] = pk2(v.z, v.w);
    lo[2 * i]     = pk2(v.x - h0, v.y - h1);
    lo[2 * i + 1] = pk2(v.z - h2, v.w - h3);
}

// =============== mma.sync NT GEMM (split fp16, fp32 accum) =================
// NPASS==3: C = Ah*Bh + Ah*Bl + Al*Bh (error ~2^-22)
// NPASS==2: C = Ah*(Bh+Bl) = Ah*B     (error ~2^-11/sqrt3, Al unused)
#define GSTR 40                        // smem row stride in halves
#define TILEB (128 * GSTR * 2)         // 10240 bytes per operand tile
#define STAGEB (4 * TILEB)             // Ah,Al,Bh,Bl slots = 40960 bytes
#define GEMM_SMEM (2 * STAGEB)         // 81920 bytes

template<int NPASS>
__device__ __forceinline__ void gemm_load_chunk(
    uint32_t sbase,
    const __half* __restrict__ Ah, const __half* __restrict__ Al,
    const __half* __restrict__ Bh, const __half* __restrict__ Bl,
    int row0, int col0, int k0, int Kdim, int tid)
{
#pragma unroll
    for (int i = 0; i < 2; ++i) {
        int v = tid + i * 256;
        int r = v >> 2, cv = v & 3;
        uint32_t soff = (uint32_t)(r * GSTR + cv * 8) * 2;
        size_t gA = (size_t)(row0 + r) * Kdim + k0 + cv * 8;
        size_t gB = (size_t)(col0 + r) * Kdim + k0 + cv * 8;
        cp16(sbase + soff,             Ah + gA);
        if (NPASS == 3) cp16(sbase + TILEB + soff, Al + gA);
        cp16(sbase + 2 * TILEB + soff, Bh + gB);
        cp16(sbase + 3 * TILEB + soff, Bl + gB);
    }
}

template<int NPASS>
__global__ __launch_bounds__(256) void gemm_mma_kernel(
    const __half* __restrict__ Ah, const __half* __restrict__ Al,
    const __half* __restrict__ Bh, const __half* __restrict__ Bl,
    float* __restrict__ C, int Mdim, int Ndim, int Kdim)
{
    extern __shared__ char smem[];
    uint32_t sm0 = smem_u32(smem);

    const int tid  = threadIdx.x;
    const int wid  = tid >> 5;
    const int lane = tid & 31;
    const int wr = wid >> 2, wc = wid & 3;
    const int m0w = wr * 64, n0w = wc * 32;
    const int row0 = blockIdx.y * 128;
    const int col0 = blockIdx.x * 128;

    const int g  = lane >> 3;
    const int fr = (g & 1) * 8 + (lane & 7);
    const int fc = (g >> 1) * 8;

    float acc[4][4][4];
#pragma unroll
    for (int a = 0; a < 4; a++)
#pragma unroll
        for (int b = 0; b < 4; b++)
#pragma unroll
            for (int d = 0; d < 4; d++) acc[a][b][d] = 0.f;

    const int nchunk = Kdim / 32;

    gemm_load_chunk<NPASS>(sm0, Ah, Al, Bh, Bl, row0, col0, 0, Kdim, tid);
    CP_COMMIT();

    for (int c = 0; c < nchunk; ++c) {
        if (c + 1 < nchunk) {
            gemm_load_chunk<NPASS>(sm0 + ((c + 1) & 1) * STAGEB, Ah, Al, Bh, Bl,
                                   row0, col0, (c + 1) * 32, Kdim, tid);
            CP_COMMIT();
            CP_WAIT(1);
        } else {
            CP_WAIT(0);
        }
        __syncthreads();

        uint32_t sb = sm0 + (c & 1) * STAGEB;
#pragma unroll
        for (int ks = 0; ks < 2; ++ks) {
            const int kb = ks * 16;
            uint32_t bh[2][4], bl[2][4];
#pragma unroll
            for (int nt2 = 0; nt2 < 2; ++nt2) {
                uint32_t ba = sb + 2 * TILEB +
                    (uint32_t)((n0w + nt2 * 16 + fr) * GSTR + kb + fc) * 2;
                ldm_x4(bh[nt2], ba);
                ldm_x4(bl[nt2], ba + TILEB);
            }
#pragma unroll
            for (int mt = 0; mt < 4; ++mt) {
                uint32_t aa = sb +
                    (uint32_t)((m0w + mt * 16 + fr) * GSTR + kb + fc) * 2;
                uint32_t ah[4], al[4];
                ldm_x4(ah, aa);
                if (NPASS == 3) ldm_x4(al, aa + TILEB);
#pragma unroll
                for (int nt = 0; nt < 4; ++nt) {
                    uint32_t b0h = bh[nt >> 1][nt & 1];
                    uint32_t b1h = bh[nt >> 1][2 + (nt & 1)];
                    uint32_t b0l = bl[nt >> 1][nt & 1];
                    uint32_t b1l = bl[nt >> 1][2 + (nt & 1)];
                    mma_f16(acc[mt][nt], ah, b0h, b1h);
                    mma_f16(acc[mt][nt], ah, b0l, b1l);
                    if (NPASS == 3) mma_f16(acc[mt][nt], al, b0h, b1h);
                }
            }
        }
        __syncthreads();
    }

#pragma unroll
    for (int mt = 0; mt < 4; ++mt) {
#pragma unroll
        for (int nt = 0; nt < 4; ++nt) {
            int r  = row0 + m0w + mt * 16 + (lane >> 2);
            int cc = col0 + n0w + nt * 8 + (lane & 3) * 2;
            float2 v0; v0.x = acc[mt][nt][0]; v0.y = acc[mt][nt][1];
            float2 v1; v1.x = acc[mt][nt][2]; v1.y = acc[mt][nt][3];
            *(float2*)&C[(size_t)r * Ndim + cc] = v0;
            *(float2*)&C[(size_t)(r + 8) * Ndim + cc] = v1;
        }
    }
}

// ------ RoPE + transpose to [B*H,S,HD] + split into hi/lo fp16 -------------
__global__ __launch_bounds__(256) void rope_split_kernel(
    const float* __restrict__ qlin, const float* __restrict__ klin,
    const float* __restrict__ vlin,
    const float* __restrict__ cosT, const float* __restrict__ sinT,
    uint32_t* __restrict__ Qh, uint32_t* __restrict__ Ql,
    uint32_t* __restrict__ Kh, uint32_t* __restrict__ Kl,
    uint32_t* __restrict__ Vh, uint32_t* __restrict__ Vl)
{
    int idx = blockIdx.x * blockDim.x + threadIdx.x;
    const int HDH = HD / 2;
    int d2 = idx % HDH;
    int h  = (idx / HDH) % NH;
    int s  = (idx / (HDH * NH)) % SEQ;
    int b  = idx / (HDH * NH * SEQ);

    size_t src = ((size_t)(b * SEQ + s)) * DIM + h * HD + 2 * d2;
    float c  = cosT[s * HDH + d2];
    float sn = sinT[s * HDH + d2];
    size_t dst = ((((size_t)(b * NH + h)) * SEQ + s) * HD + 2 * d2) >> 1;

    float q0 = qlin[src], q1 = qlin[src + 1];
    float k0 = klin[src], k1 = klin[src + 1];
    float v0 = vlin[src], v1 = vlin[src + 1];
    float qa = q0 * c - q1 * sn, qb = q0 * sn + q1 * c;
    float ka = k0 * c - k1 * sn, kb = k0 * sn + k1 * c;

    Qh[dst] = pk2(qa, qb); Ql[dst] = pk2(qa - hrt(qa), qb - hrt(qb));
    Kh[dst] = pk2(ka, kb); Kl[dst] = pk2(ka - hrt(ka), kb - hrt(kb));
    Vh[dst] = pk2(v0, v1); Vl[dst] = pk2(v0 - hrt(v0), v1 - hrt(v1));
}

// ============= Flash attention via mma.sync (split fp16) ===================
// CTA: 128 q-rows, 8 warps x 16 rows. BKV=64. double-buffered K/V hi/lo.
// QK^T: 3-pass (softmax-amplified path). PV: 2-pass (P hi only).
#define FQS   272                  // smem row stride in BYTES (136 halves)
#define FB_QH 0
#define FB_QL 34816                // 128*272
#define FB_ST 69632
#define FSTG  69632                // 4 * 64*272
#define FB_KH 0
#define FB_KL 17408
#define FB_VH 34816
#define FB_VL 52224
#define FLASH_SMEM (FB_ST + 2 * FSTG)   // 208896

__global__ __launch_bounds__(256, 1) void flash_mma_kernel(
    const __half* __restrict__ Qh, const __half* __restrict__ Ql,
    const __half* __restrict__ Kh, const __half* __restrict__ Kl,
    const __half* __restrict__ Vh, const __half* __restrict__ Vl,
    uint32_t* __restrict__ outH)
{
    extern __shared__ char smem[];
    uint32_t s0 = smem_u32(smem);
    const int bh  = blockIdx.x;
    const int qt  = (int)gridDim.y - 1 - (int)blockIdx.y;   // big tiles first
    const int tid = threadIdx.x, wid = tid >> 5, lane = tid & 31;
    const int m0w = wid * 16;
    const int gg  = lane >> 3;
    const int fr  = (gg & 1) * 8 + (lane & 7);
    const int fc  = (gg >> 1) * 8;
    const int q0  = qt * 128;
    const size_t hoff = (size_t)bh * SEQ * HD;
    const float scale = 0.08838834764831845f;   // 1/sqrt(128)

    {
        const __half* gq_h = Qh + hoff + (size_t)q0 * HD;
        const __half* gq_l = Ql + hoff + (size_t)q0 * HD;
#pragma unroll
        for (int i = 0; i < 8; i++) {
            int v = tid + (i << 8); int r = v >> 4, c = v & 15;
            uint32_t so = (uint32_t)(r * FQS + c * 16);
            cp16(s0 + FB_QH + so, gq_h + r * HD + c * 8);
            cp16(s0 + FB_QL + so, gq_l + r * HD + c * 8);
        }
        uint32_t sb = s0 + FB_ST;
#pragma unroll
        for (int i = 0; i < 4; i++) {
            int v = tid + (i << 8); int r = v >> 4, c = v & 15;
            uint32_t so = (uint32_t)(r * FQS + c * 16);
            size_t go = hoff + r * HD + c * 8;
            cp16(sb + FB_KH + so, Kh + go);
            cp16(sb + FB_KL + so, Kl + go);
            cp16(sb + FB_VH + so, Vh + go);
            cp16(sb + FB_VL + so, Vl + go);
        }
    }
    CP_COMMIT();

    float O[16][4];
#pragma unroll
    for (int i = 0; i < 16; i++)
#pragma unroll
        for (int j = 0; j < 4; j++) O[i][j] = 0.f;
    float m0 = -1e30f, m1 = -1e30f, l0 = 0.f, l1 = 0.f;

    const int last  = 2 * qt + 1;
    const int r0g   = q0 + m0w + (lane >> 2);
    const int cbase = (lane & 3) * 2;

    for (int kt = 0; kt <= last; kt++) {
        const int stg = kt & 1;
        if (kt < last) {
            uint32_t sb = s0 + FB_ST + (stg ^ 1) * FSTG;
            size_t kvo = hoff + (size_t)(kt + 1) * 64 * HD;
#pragma unroll
            for (int i = 0; i < 4; i++) {
                int v = tid + (i << 8); int r = v >> 4, c = v & 15;
                uint32_t so = (uint32_t)(r * FQS + c * 16);
                size_t go = kvo + r * HD + c * 8;
                cp16(sb + FB_KH + so, Kh + go);
                cp16(sb + FB_KL + so, Kl + go);
                cp16(sb + FB_VH + so, Vh + go);
                cp16(sb + FB_VL + so, Vl + go);
            }
            CP_COMMIT();
            CP_WAIT(1);
        } else {
            CP_WAIT(0);
        }
        __syncthreads();

        uint32_t sb = s0 + FB_ST + stg * FSTG;

        // ---- S = Q K^T (3-pass split) ----
        float Sv[8][4];
#pragma unroll
        for (int i = 0; i < 8; i++)
#pragma unroll
            for (int j = 0; j < 4; j++) Sv[i][j] = 0.f;

#pragma unroll
        for (int kk = 0; kk < 8; kk++) {
            uint32_t qoff = (uint32_t)((m0w + fr) * FQS + (kk * 16 + fc) * 2);
            uint32_t ah[4], al[4];
            ldm_x4(ah, s0 + FB_QH + qoff);
            ldm_x4(al, s0 + FB_QL + qoff);
#pragma unroll
            for (int nt2 = 0; nt2 < 4; nt2++) {
                uint32_t koff = (uint32_t)((nt2 * 16 + fr) * FQS + (kk * 16 + fc) * 2);
                uint32_t bh4[4], bl4[4];
                ldm_x4(bh4, sb + FB_KH + koff);
                ldm_x4(bl4, sb + FB_KL + koff);
                mma_f16(Sv[2 * nt2],     ah, bh4[0], bh4[2]);
                mma_f16(Sv[2 * nt2 + 1], ah, bh4[1], bh4[3]);
                mma_f16(Sv[2 * nt2],     ah, bl4[0], bl4[2]);
                mma_f16(Sv[2 * nt2 + 1], ah, bl4[1], bl4[3]);
                mma_f16(Sv[2 * nt2],     al, bh4[0], bh4[2]);
                mma_f16(Sv[2 * nt2 + 1], al, bh4[1], bh4[3]);
            }
        }

        // ---- scale + causal mask ----
        if (kt >= 2 * qt) {
#pragma unroll
            for (int nt = 0; nt < 8; nt++) {
                int c0 = kt * 64 + nt * 8 + cbase;
                Sv[nt][0] = (c0     > r0g)     ? -1e30f : Sv[nt][0] * scale;
                Sv[nt][1] = (c0 + 1 > r0g)     ? -1e30f : Sv[nt][1] * scale;
                Sv[nt][2] = (c0     > r0g + 8) ? -1e30f : Sv[nt][2] * scale;
                Sv[nt][3] = (c0 + 1 > r0g + 8) ? -1e30f : Sv[nt][3] * scale;
            }
        } else {
#pragma unroll
            for (int nt = 0; nt < 8; nt++)
#pragma unroll
                for (int j = 0; j < 4; j++) Sv[nt][j] *= scale;
        }

        // ---- online softmax (rows r0g and r0g+8, 4 lanes each) ----
        float mx0 = -1e30f, mx1 = -1e30f;
#pragma unroll
        for (int nt = 0; nt < 8; nt++) {
            mx0 = fmaxf(mx0, fmaxf(Sv[nt][0], Sv[nt][1]));
            mx1 = fmaxf(mx1, fmaxf(Sv[nt][2], Sv[nt][3]));
        }
        mx0 = fmaxf(mx0, __shfl_xor_sync(0xffffffffu, mx0, 1));
        mx0 = fmaxf(mx0, __shfl_xor_sync(0xffffffffu, mx0, 2));
        mx1 = fmaxf(mx1, __shfl_xor_sync(0xffffffffu, mx1, 1));
        mx1 = fmaxf(mx1, __shfl_xor_sync(0xffffffffu, mx1, 2));

        float mn0 = fmaxf(m0, mx0), mn1 = fmaxf(m1, mx1);
        float al0 = __expf(m0 - mn0), al1 = __expf(m1 - mn1);
        float sum0 = 0.f, sum1 = 0.f;
#pragma unroll
        for (int nt = 0; nt < 8; nt++) {
            Sv[nt][0] = __expf(Sv[nt][0] - mn0); sum0 += Sv[nt][0];
            Sv[nt][1] = __expf(Sv[nt][1] - mn0); sum0 += Sv[nt][1];
            Sv[nt][2] = __expf(Sv[nt][2] - mn1); sum1 += Sv[nt][2];
            Sv[nt][3] = __expf(Sv[nt][3] - mn1); sum1 += Sv[nt][3];
        }
        sum0 += __shfl_xor_sync(0xffffffffu, sum0, 1);
        sum0 += __shfl_xor_sync(0xffffffffu, sum0, 2);
        sum1 += __shfl_xor_sync(0xffffffffu, sum1, 1);
        sum1 += __shfl_xor_sync(0xffffffffu, sum1, 2);
        l0 = l0 * al0 + sum0; l1 = l1 * al1 + sum1;
        m0 = mn0; m1 = mn1;
#pragma unroll
        for (int nt = 0; nt < 16; nt++) {
            O[nt][0] *= al0; O[nt][1] *= al0;
            O[nt][2] *= al1; O[nt][3] *= al1;
        }

        // ---- O += P V (2-pass: P hi only, V hi+lo) ----
#pragma unroll
        for (int kk = 0; kk < 4; kk++) {
            uint32_t pah[4];
            pah[0] = pk2(Sv[2 * kk][0],     Sv[2 * kk][1]);
            pah[1] = pk2(Sv[2 * kk][2],     Sv[2 * kk][3]);
            pah[2] = pk2(Sv[2 * kk + 1][0], Sv[2 * kk + 1][1]);
            pah[3] = pk2(Sv[2 * kk + 1][2], Sv[2 * kk + 1][3]);
#pragma unroll
            for (int j = 0; j < 8; j++) {
                uint32_t vo = (uint32_t)((kk * 16 + fr) * FQS + (j * 16 + fc) * 2);
                uint32_t vh4[4], vl4[4];
                ldm_x4t(vh4, sb + FB_VH + vo);
                ldm_x4t(vl4, sb + FB_VL + vo);
                mma_f16(O[2 * j],     pah, vh4[0], vh4[1]);
                mma_f16(O[2 * j + 1], pah, vh4[2], vh4[3]);
                mma_f16(O[2 * j],     pah, vl4[0], vl4[1]);
                mma_f16(O[2 * j + 1], pah, vl4[2], vl4[3]);
            }
        }
        __syncthreads();
    }

    // ---- epilogue: normalize, store hi fp16 to [B,S,DIM] ----
    float inv0 = 1.f / l0, inv1 = 1.f / l1;
    const int b = bh >> 4, h = bh & 15;
    const int s_row = q0 + m0w + (lane >> 2);
#pragma unroll
    for (int nt = 0; nt < 16; nt++) {
        int col = h * HD + nt * 8 + cbase;
        {
            size_t o = (((size_t)(b * SEQ + s_row)) * DIM + col) >> 1;
            outH[o] = pk2(O[nt][0] * inv0, O[nt][1] * inv0);
        }
        {
            size_t o = (((size_t)(b * SEQ + s_row + 8)) * DIM + col) >> 1;
            outH[o] = pk2(O[nt][2] * inv1, O[nt][3] * inv1);
        }
    }
}

// ---------------------------------------------------------------------------
extern "C" void kernel_launch(void* const* d_in, const int* in_sizes, int n_in,
                              void* d_out, int out_size)
{
    const float* x    = (const float*)d_in[0];
    const float* wq   = (const float*)d_in[1];
    const float* wk   = (const float*)d_in[2];
    const float* wv   = (const float*)d_in[3];
    const float* wo   = (const float*)d_in[4];
    const float* fcos = (const float*)d_in[5];
    const float* fsin = (const float*)d_in[6];
    float* out = (float*)d_out;

    float *qlin, *klin, *vlin;
    cudaGetSymbolAddress((void**)&qlin, g_qlin);
    cudaGetSymbolAddress((void**)&klin, g_klin);
    cudaGetSymbolAddress((void**)&vlin, g_vlin);

    __half *xh, *xl, *wqh, *wql, *wkh, *wkl, *wvh, *wvl, *woh, *wol, *ah;
    cudaGetSymbolAddress((void**)&xh,  g_xh);
    cudaGetSymbolAddress((void**)&xl,  g_xl);
    cudaGetSymbolAddress((void**)&wqh, g_wqh);
    cudaGetSymbolAddress((void**)&wql, g_wql);
    cudaGetSymbolAddress((void**)&wkh, g_wkh);
    cudaGetSymbolAddress((void**)&wkl, g_wkl);
    cudaGetSymbolAddress((void**)&wvh, g_wvh);
    cudaGetSymbolAddress((void**)&wvl, g_wvl);
    cudaGetSymbolAddress((void**)&woh, g_woh);
    cudaGetSymbolAddress((void**)&wol, g_wol);
    cudaGetSymbolAddress((void**)&ah,  g_ah);

    __half *Qh, *Ql, *Kh, *Kl, *Vh, *Vl;
    cudaGetSymbolAddress((void**)&Qh, g_Qh);
    cudaGetSymbolAddress((void**)&Ql, g_Ql);
    cudaGetSymbolAddress((void**)&Kh, g_Kh);
    cudaGetSymbolAddress((void**)&Kl, g_Kl);
    cudaGetSymbolAddress((void**)&Vh, g_Vh);
    cudaGetSymbolAddress((void**)&Vl, g_Vl);

    cudaFuncSetAttribute(gemm_mma_kernel<3>,
                         cudaFuncAttributeMaxDynamicSharedMemorySize, GEMM_SMEM);
    cudaFuncSetAttribute(gemm_mma_kernel<2>,
                         cudaFuncAttributeMaxDynamicSharedMemorySize, GEMM_SMEM);
    cudaFuncSetAttribute(flash_mma_kernel,
                         cudaFuncAttributeMaxDynamicSharedMemorySize, FLASH_SMEM);

    const int nx4 = (MROWS * DIM) / 4;
    const int nw4 = (DIM * DIM) / 4;
    split_kernel<<<(nx4 + 255) / 256, 256>>>((const float4*)x,
        (uint32_t*)xh, (uint32_t*)xl, nx4);
    split_kernel<<<(nw4 + 255) / 256, 256>>>((const float4*)wq,
        (uint32_t*)wqh, (uint32_t*)wql, nw4);
    split_kernel<<<(nw4 + 255) / 256, 256>>>((const float4*)wk,
        (uint32_t*)wkh, (uint32_t*)wkl, nw4);
    split_kernel<<<(nw4 + 255) / 256, 256>>>((const float4*)wv,
        (uint32_t*)wvh, (uint32_t*)wvl, nw4);
    split_kernel<<<(nw4 + 255) / 256, 256>>>((const float4*)wo,
        (uint32_t*)woh, (uint32_t*)wol, nw4);

    dim3 gGrid(DIM / 128, MROWS / 128);
    // Q, K projections: 3-pass (softmax-amplified path)
    gemm_mma_kernel<3><<<gGrid, 256, GEMM_SMEM>>>(xh, xl, wqh, wql, qlin, MROWS, DIM, DIM);
    gemm_mma_kernel<3><<<gGrid, 256, GEMM_SMEM>>>(xh, xl, wkh, wkl, klin, MROWS, DIM, DIM);
    // V projection: 2-pass
    gemm_mma_kernel<2><<<gGrid, 256, GEMM_SMEM>>>(xh, xh, wvh, wvl, vlin, MROWS, DIM, DIM);

    int ropeElems = BSZ * SEQ * NH * (HD / 2);
    rope_split_kernel<<<ropeElems / 256, 256>>>(qlin, klin, vlin, fcos, fsin,
        (uint32_t*)Qh, (uint32_t*)Ql, (uint32_t*)Kh, (uint32_t*)Kl,
        (uint32_t*)Vh, (uint32_t*)Vl);

    flash_mma_kernel<<<dim3(BSZ * NH, SEQ / 128), 256, FLASH_SMEM>>>(
        Qh, Ql, Kh, Kl, Vh, Vl, (uint32_t*)ah);

    // output projection: 2-pass (A = attn hi only)
    gemm_mma_kernel<2><<<gGrid, 256, GEMM_SMEM>>>(ah, ah, woh, wol, out, MROWS, DIM, DIM);
}

// round 7
// speedup vs baseline: 4.5234x; 1.2416x over previous
#include <cuda_runtime.h>
#include <cuda_fp16.h>
#include <math.h>
#include <stdint.h>

#define BSZ 2
#define SEQ 2048
#define DIM 2048
#define NH  16
#define HD  128
#define MROWS (BSZ*SEQ)          // 4096

// ---------------- scratch (static device globals; no allocation) -----------
__device__ float g_qlin[(size_t)MROWS * DIM];
__device__ float g_klin[(size_t)MROWS * DIM];
__device__ float g_vlin[(size_t)MROWS * DIM];

// fp16 operands
__device__ __half g_xh[(size_t)MROWS * DIM];
__device__ __half g_wqh[(size_t)DIM * DIM];
__device__ __half g_wql[(size_t)DIM * DIM];
__device__ __half g_wkh[(size_t)DIM * DIM];
__device__ __half g_wkl[(size_t)DIM * DIM];
__device__ __half g_wvh[(size_t)DIM * DIM];
__device__ __half g_wvl[(size_t)DIM * DIM];
__device__ __half g_woh[(size_t)DIM * DIM];
__device__ __half g_wol[(size_t)DIM * DIM];
__device__ __half g_ah[(size_t)MROWS * DIM];     // attention out (hi only)

// per-head fp16 Q(hi), K(hi/lo), V(hi/lo)  [B*NH, SEQ, HD]
#define HELEMS ((size_t)BSZ * NH * SEQ * HD)
__device__ __half g_Qh[HELEMS];
__device__ __half g_Kh[HELEMS];
__device__ __half g_Kl[HELEMS];
__device__ __half g_Vh[HELEMS];
__device__ __half g_Vl[HELEMS];

// ======================= helpers ==========================================
__device__ __forceinline__ uint32_t smem_u32(const void* p) {
    uint32_t a;
    asm("{ .reg .u64 t; cvta.to.shared.u64 t, %1; cvt.u32.u64 %0, t; }"
        : "=r"(a) : "l"(p));
    return a;
}
__device__ __forceinline__ void cp16(uint32_t saddr, const void* g) {
    asm volatile("cp.async.ca.shared.global [%0], [%1], 16;"
                 :: "r"(saddr), "l"(g));
}
#define CP_COMMIT() asm volatile("cp.async.commit_group;" ::: "memory")
#define CP_WAIT(n)  asm volatile("cp.async.wait_group %0;" :: "n"(n) : "memory")

__device__ __forceinline__ void ldm_x4(uint32_t* d, uint32_t addr) {
    asm volatile("ldmatrix.sync.aligned.m8n8.x4.shared.b16 {%0,%1,%2,%3}, [%4];"
                 : "=r"(d[0]), "=r"(d[1]), "=r"(d[2]), "=r"(d[3]) : "r"(addr));
}
__device__ __forceinline__ void ldm_x4t(uint32_t* d, uint32_t addr) {
    asm volatile("ldmatrix.sync.aligned.m8n8.x4.trans.shared.b16 {%0,%1,%2,%3}, [%4];"
                 : "=r"(d[0]), "=r"(d[1]), "=r"(d[2]), "=r"(d[3]) : "r"(addr));
}
__device__ __forceinline__ void mma_f16(float* c, const uint32_t* a,
                                        uint32_t b0, uint32_t b1) {
    asm volatile(
        "mma.sync.aligned.m16n8k16.row.col.f32.f16.f16.f32 "
        "{%0,%1,%2,%3}, {%4,%5,%6,%7}, {%8,%9}, {%0,%1,%2,%3};"
        : "+f"(c[0]), "+f"(c[1]), "+f"(c[2]), "+f"(c[3])
        : "r"(a[0]), "r"(a[1]), "r"(a[2]), "r"(a[3]), "r"(b0), "r"(b1));
}
// pack {lo, hi} floats -> f16x2 (lo in low half)
__device__ __forceinline__ uint32_t pk2(float lo, float hi) {
    uint32_t r;
    asm("cvt.rn.f16x2.f32 %0, %1, %2;" : "=r"(r) : "f"(hi), "f"(lo));
    return r;
}
__device__ __forceinline__ float hrt(float v) {   // fp16 round-trip
    return __half2float(__float2half_rn(v));
}

// =================== split fp32 -> (hi, lo) fp16 ===========================
__global__ __launch_bounds__(256) void split_kernel(
    const float4* __restrict__ in, uint32_t* __restrict__ hi,
    uint32_t* __restrict__ lo, int n4)
{
    int i = blockIdx.x * blockDim.x + threadIdx.x;
    if (i >= n4) return;
    float4 v = in[i];
    float h0 = hrt(v.x), h1 = hrt(v.y), h2 = hrt(v.z), h3 = hrt(v.w);
    hi[2 * i]     = pk2(v.x, v.y);
    hi[2 * i + 1] = pk2(v.z, v.w);
    lo[2 * i]     = pk2(v.x - h0, v.y - h1);
    lo[2 * i + 1] = pk2(v.z - h2, v.w - h3);
}

// hi-only convert (A-side operands of 2-pass GEMMs)
__global__ __launch_bounds__(256) void cvt_hi_kernel(
    const float4* __restrict__ in, uint32_t* __restrict__ hi, int n4)
{
    int i = blockIdx.x * blockDim.x + threadIdx.x;
    if (i >= n4) return;
    float4 v = in[i];
    hi[2 * i]     = pk2(v.x, v.y);
    hi[2 * i + 1] = pk2(v.z, v.w);
}

// =============== mma.sync NT GEMM (2-pass split fp16, fp32 accum) ==========
// C = Ah*Bh + Ah*Bl = Ah*B  (error ~2^-12/sqrt3 relative)
#define GSTR 40                        // smem row stride in halves
#define TILEB (128 * GSTR * 2)         // 10240 bytes per operand tile
#define STAGEB (4 * TILEB)             // Ah,(pad),Bh,Bl slots = 40960 bytes
#define GEMM_SMEM (2 * STAGEB)         // 81920 bytes

__device__ __forceinline__ void gemm_load_chunk(
    uint32_t sbase,
    const __half* __restrict__ Ah,
    const __half* __restrict__ Bh, const __half* __restrict__ Bl,
    int row0, int col0, int k0, int Kdim, int tid)
{
#pragma unroll
    for (int i = 0; i < 2; ++i) {
        int v = tid + i * 256;
        int r = v >> 2, cv = v & 3;
        uint32_t soff = (uint32_t)(r * GSTR + cv * 8) * 2;
        size_t gA = (size_t)(row0 + r) * Kdim + k0 + cv * 8;
        size_t gB = (size_t)(col0 + r) * Kdim + k0 + cv * 8;
        cp16(sbase + soff,             Ah + gA);
        cp16(sbase + 2 * TILEB + soff, Bh + gB);
        cp16(sbase + 3 * TILEB + soff, Bl + gB);
    }
}

__global__ __launch_bounds__(256) void gemm_mma_kernel(
    const __half* __restrict__ Ah,
    const __half* __restrict__ Bh, const __half* __restrict__ Bl,
    float* __restrict__ C, int Mdim, int Ndim, int Kdim)
{
    extern __shared__ char smem[];
    uint32_t sm0 = smem_u32(smem);

    const int tid  = threadIdx.x;
    const int wid  = tid >> 5;
    const int lane = tid & 31;
    const int wr = wid >> 2, wc = wid & 3;
    const int m0w = wr * 64, n0w = wc * 32;
    const int row0 = blockIdx.y * 128;
    const int col0 = blockIdx.x * 128;

    const int g  = lane >> 3;
    const int fr = (g & 1) * 8 + (lane & 7);
    const int fc = (g >> 1) * 8;

    float acc[4][4][4];
#pragma unroll
    for (int a = 0; a < 4; a++)
#pragma unroll
        for (int b = 0; b < 4; b++)
#pragma unroll
            for (int d = 0; d < 4; d++) acc[a][b][d] = 0.f;

    const int nchunk = Kdim / 32;

    gemm_load_chunk(sm0, Ah, Bh, Bl, row0, col0, 0, Kdim, tid);
    CP_COMMIT();

    for (int c = 0; c < nchunk; ++c) {
        if (c + 1 < nchunk) {
            gemm_load_chunk(sm0 + ((c + 1) & 1) * STAGEB, Ah, Bh, Bl,
                            row0, col0, (c + 1) * 32, Kdim, tid);
            CP_COMMIT();
            CP_WAIT(1);
        } else {
            CP_WAIT(0);
        }
        __syncthreads();

        uint32_t sb = sm0 + (c & 1) * STAGEB;
#pragma unroll
        for (int ks = 0; ks < 2; ++ks) {
            const int kb = ks * 16;
            uint32_t bh[2][4], bl[2][4];
#pragma unroll
            for (int nt2 = 0; nt2 < 2; ++nt2) {
                uint32_t ba = sb + 2 * TILEB +
                    (uint32_t)((n0w + nt2 * 16 + fr) * GSTR + kb + fc) * 2;
                ldm_x4(bh[nt2], ba);
                ldm_x4(bl[nt2], ba + TILEB);
            }
#pragma unroll
            for (int mt = 0; mt < 4; ++mt) {
                uint32_t aa = sb +
                    (uint32_t)((m0w + mt * 16 + fr) * GSTR + kb + fc) * 2;
                uint32_t ah[4];
                ldm_x4(ah, aa);
#pragma unroll
                for (int nt = 0; nt < 4; ++nt) {
                    uint32_t b0h = bh[nt >> 1][nt & 1];
                    uint32_t b1h = bh[nt >> 1][2 + (nt & 1)];
                    uint32_t b0l = bl[nt >> 1][nt & 1];
                    uint32_t b1l = bl[nt >> 1][2 + (nt & 1)];
                    mma_f16(acc[mt][nt], ah, b0h, b1h);
                    mma_f16(acc[mt][nt], ah, b0l, b1l);
                }
            }
        }
        __syncthreads();
    }

#pragma unroll
    for (int mt = 0; mt < 4; ++mt) {
#pragma unroll
        for (int nt = 0; nt < 4; ++nt) {
            int r  = row0 + m0w + mt * 16 + (lane >> 2);
            int cc = col0 + n0w + nt * 8 + (lane & 3) * 2;
            float2 v0; v0.x = acc[mt][nt][0]; v0.y = acc[mt][nt][1];
            float2 v1; v1.x = acc[mt][nt][2]; v1.y = acc[mt][nt][3];
            *(float2*)&C[(size_t)r * Ndim + cc] = v0;
            *(float2*)&C[(size_t)(r + 8) * Ndim + cc] = v1;
        }
    }
}

// ------ RoPE + transpose to [B*H,S,HD] + split into fp16 -------------------
__global__ __launch_bounds__(256) void rope_split_kernel(
    const float* __restrict__ qlin, const float* __restrict__ klin,
    const float* __restrict__ vlin,
    const float* __restrict__ cosT, const float* __restrict__ sinT,
    uint32_t* __restrict__ Qh,
    uint32_t* __restrict__ Kh, uint32_t* __restrict__ Kl,
    uint32_t* __restrict__ Vh, uint32_t* __restrict__ Vl)
{
    int idx = blockIdx.x * blockDim.x + threadIdx.x;
    const int HDH = HD / 2;
    int d2 = idx % HDH;
    int h  = (idx / HDH) % NH;
    int s  = (idx / (HDH * NH)) % SEQ;
    int b  = idx / (HDH * NH * SEQ);

    size_t src = ((size_t)(b * SEQ + s)) * DIM + h * HD + 2 * d2;
    float c  = cosT[s * HDH + d2];
    float sn = sinT[s * HDH + d2];
    size_t dst = ((((size_t)(b * NH + h)) * SEQ + s) * HD + 2 * d2) >> 1;

    float q0 = qlin[src], q1 = qlin[src + 1];
    float k0 = klin[src], k1 = klin[src + 1];
    float v0 = vlin[src], v1 = vlin[src + 1];
    float qa = q0 * c - q1 * sn, qb = q0 * sn + q1 * c;
    float ka = k0 * c - k1 * sn, kb = k0 * sn + k1 * c;

    Qh[dst] = pk2(qa, qb);
    Kh[dst] = pk2(ka, kb); Kl[dst] = pk2(ka - hrt(ka), kb - hrt(kb));
    Vh[dst] = pk2(v0, v1); Vl[dst] = pk2(v0 - hrt(v0), v1 - hrt(v1));
}

// ============= Flash attention via mma.sync (2-pass fp16) ==================
// CTA: 128 q-rows, 8 warps x 16 rows. BKV=64. double-buffered K/V hi/lo.
// QK^T: Qh*(Kh+Kl).  PV: Ph*(Vh+Vl).
#define FQS   272                  // smem row stride in BYTES (136 halves)
#define FB_QH 0
#define FB_ST 34816                // 128*272
#define FSTG  69632                // 4 * 64*272
#define FB_KH 0
#define FB_KL 17408
#define FB_VH 34816
#define FB_VL 52224
#define FLASH_SMEM (FB_ST + 2 * FSTG)   // 174080

__global__ __launch_bounds__(256, 1) void flash_mma_kernel(
    const __half* __restrict__ Qh,
    const __half* __restrict__ Kh, const __half* __restrict__ Kl,
    const __half* __restrict__ Vh, const __half* __restrict__ Vl,
    uint32_t* __restrict__ outH)
{
    extern __shared__ char smem[];
    uint32_t s0 = smem_u32(smem);
    const int bh  = blockIdx.x;
    const int qt  = (int)gridDim.y - 1 - (int)blockIdx.y;   // big tiles first
    const int tid = threadIdx.x, wid = tid >> 5, lane = tid & 31;
    const int m0w = wid * 16;
    const int gg  = lane >> 3;
    const int fr  = (gg & 1) * 8 + (lane & 7);
    const int fc  = (gg >> 1) * 8;
    const int q0  = qt * 128;
    const size_t hoff = (size_t)bh * SEQ * HD;
    const float scale = 0.08838834764831845f;   // 1/sqrt(128)

    {
        const __half* gq_h = Qh + hoff + (size_t)q0 * HD;
#pragma unroll
        for (int i = 0; i < 8; i++) {
            int v = tid + (i << 8); int r = v >> 4, c = v & 15;
            if (i < 8) {
                uint32_t so = (uint32_t)(r * FQS + c * 16);
                cp16(s0 + FB_QH + so, gq_h + r * HD + c * 8);
            }
        }
        uint32_t sb = s0 + FB_ST;
#pragma unroll
        for (int i = 0; i < 4; i++) {
            int v = tid + (i << 8); int r = v >> 4, c = v & 15;
            uint32_t so = (uint32_t)(r * FQS + c * 16);
            size_t go = hoff + r * HD + c * 8;
            cp16(sb + FB_KH + so, Kh + go);
            cp16(sb + FB_KL + so, Kl + go);
            cp16(sb + FB_VH + so, Vh + go);
            cp16(sb + FB_VL + so, Vl + go);
        }
    }
    CP_COMMIT();

    float O[16][4];
#pragma unroll
    for (int i = 0; i < 16; i++)
#pragma unroll
        for (int j = 0; j < 4; j++) O[i][j] = 0.f;
    float m0 = -1e30f, m1 = -1e30f, l0 = 0.f, l1 = 0.f;

    const int last  = 2 * qt + 1;
    const int r0g   = q0 + m0w + (lane >> 2);
    const int cbase = (lane & 3) * 2;

    for (int kt = 0; kt <= last; kt++) {
        const int stg = kt & 1;
        if (kt < last) {
            uint32_t sb = s0 + FB_ST + (stg ^ 1) * FSTG;
            size_t kvo = hoff + (size_t)(kt + 1) * 64 * HD;
#pragma unroll
            for (int i = 0; i < 4; i++) {
                int v = tid + (i << 8); int r = v >> 4, c = v & 15;
                uint32_t so = (uint32_t)(r * FQS + c * 16);
                size_t go = kvo + r * HD + c * 8;
                cp16(sb + FB_KH + so, Kh + go);
                cp16(sb + FB_KL + so, Kl + go);
                cp16(sb + FB_VH + so, Vh + go);
                cp16(sb + FB_VL + so, Vl + go);
            }
            CP_COMMIT();
            CP_WAIT(1);
        } else {
            CP_WAIT(0);
        }
        __syncthreads();

        uint32_t sb = s0 + FB_ST + stg * FSTG;

        // ---- S = Q K^T (2-pass: Qh * (Kh + Kl)) ----
        float Sv[8][4];
#pragma unroll
        for (int i = 0; i < 8; i++)
#pragma unroll
            for (int j = 0; j < 4; j++) Sv[i][j] = 0.f;

#pragma unroll
        for (int kk = 0; kk < 8; kk++) {
            uint32_t qoff = (uint32_t)((m0w + fr) * FQS + (kk * 16 + fc) * 2);
            uint32_t ah[4];
            ldm_x4(ah, s0 + FB_QH + qoff);
#pragma unroll
            for (int nt2 = 0; nt2 < 4; nt2++) {
                uint32_t koff = (uint32_t)((nt2 * 16 + fr) * FQS + (kk * 16 + fc) * 2);
                uint32_t bh4[4], bl4[4];
                ldm_x4(bh4, sb + FB_KH + koff);
                ldm_x4(bl4, sb + FB_KL + koff);
                mma_f16(Sv[2 * nt2],     ah, bh4[0], bh4[2]);
                mma_f16(Sv[2 * nt2 + 1], ah, bh4[1], bh4[3]);
                mma_f16(Sv[2 * nt2],     ah, bl4[0], bl4[2]);
                mma_f16(Sv[2 * nt2 + 1], ah, bl4[1], bl4[3]);
            }
        }

        // ---- scale + causal mask ----
        if (kt >= 2 * qt) {
#pragma unroll
            for (int nt = 0; nt < 8; nt++) {
                int c0 = kt * 64 + nt * 8 + cbase;
                Sv[nt][0] = (c0     > r0g)     ? -1e30f : Sv[nt][0] * scale;
                Sv[nt][1] = (c0 + 1 > r0g)     ? -1e30f : Sv[nt][1] * scale;
                Sv[nt][2] = (c0     > r0g + 8) ? -1e30f : Sv[nt][2] * scale;
                Sv[nt][3] = (c0 + 1 > r0g + 8) ? -1e30f : Sv[nt][3] * scale;
            }
        } else {
#pragma unroll
            for (int nt = 0; nt < 8; nt++)
#pragma unroll
                for (int j = 0; j < 4; j++) Sv[nt][j] *= scale;
        }

        // ---- online softmax (rows r0g and r0g+8, 4 lanes each) ----
        float mx0 = -1e30f, mx1 = -1e30f;
#pragma unroll
        for (int nt = 0; nt < 8; nt++) {
            mx0 = fmaxf(mx0, fmaxf(Sv[nt][0], Sv[nt][1]));
            mx1 = fmaxf(mx1, fmaxf(Sv[nt][2], Sv[nt][3]));
        }
        mx0 = fmaxf(mx0, __shfl_xor_sync(0xffffffffu, mx0, 1));
        mx0 = fmaxf(mx0, __shfl_xor_sync(0xffffffffu, mx0, 2));
        mx1 = fmaxf(mx1, __shfl_xor_sync(0xffffffffu, mx1, 1));
        mx1 = fmaxf(mx1, __shfl_xor_sync(0xffffffffu, mx1, 2));

        float mn0 = fmaxf(m0, mx0), mn1 = fmaxf(m1, mx1);
        float al0 = __expf(m0 - mn0), al1 = __expf(m1 - mn1);
        float sum0 = 0.f, sum1 = 0.f;
#pragma unroll
        for (int nt = 0; nt < 8; nt++) {
            Sv[nt][0] = __expf(Sv[nt][0] - mn0); sum0 += Sv[nt][0];
            Sv[nt][1] = __expf(Sv[nt][1] - mn0); sum0 += Sv[nt][1];
            Sv[nt][2] = __expf(Sv[nt][2] - mn1); sum1 += Sv[nt][2];
            Sv[nt][3] = __expf(Sv[nt][3] - mn1); sum1 += Sv[nt][3];
        }
        sum0 += __shfl_xor_sync(0xffffffffu, sum0, 1);
        sum0 += __shfl_xor_sync(0xffffffffu, sum0, 2);
        sum1 += __shfl_xor_sync(0xffffffffu, sum1, 1);
        sum1 += __shfl_xor_sync(0xffffffffu, sum1, 2);
        l0 = l0 * al0 + sum0; l1 = l1 * al1 + sum1;
        m0 = mn0; m1 = mn1;
#pragma unroll
        for (int nt = 0; nt < 16; nt++) {
            O[nt][0] *= al0; O[nt][1] *= al0;
            O[nt][2] *= al1; O[nt][3] *= al1;
        }

        // ---- O += P V (2-pass: P hi only, V hi+lo) ----
#pragma unroll
        for (int kk = 0; kk < 4; kk++) {
            uint32_t pah[4];
            pah[0] = pk2(Sv[2 * kk][0],     Sv[2 * kk][1]);
            pah[1] = pk2(Sv[2 * kk][2],     Sv[2 * kk][3]);
            pah[2] = pk2(Sv[2 * kk + 1][0], Sv[2 * kk + 1][1]);
            pah[3] = pk2(Sv[2 * kk + 1][2], Sv[2 * kk + 1][3]);
#pragma unroll
            for (int j = 0; j < 8; j++) {
                uint32_t vo = (uint32_t)((kk * 16 + fr) * FQS + (j * 16 + fc) * 2);
                uint32_t vh4[4], vl4[4];
                ldm_x4t(vh4, sb + FB_VH + vo);
                ldm_x4t(vl4, sb + FB_VL + vo);
                mma_f16(O[2 * j],     pah, vh4[0], vh4[1]);
                mma_f16(O[2 * j + 1], pah, vh4[2], vh4[3]);
                mma_f16(O[2 * j],     pah, vl4[0], vl4[1]);
                mma_f16(O[2 * j + 1], pah, vl4[2], vl4[3]);
            }
        }
        __syncthreads();
    }

    // ---- epilogue: normalize, store hi fp16 to [B,S,DIM] ----
    float inv0 = 1.f / l0, inv1 = 1.f / l1;
    const int b = bh >> 4, h = bh & 15;
    const int s_row = q0 + m0w + (lane >> 2);
#pragma unroll
    for (int nt = 0; nt < 16; nt++) {
        int col = h * HD + nt * 8 + cbase;
        {
            size_t o = (((size_t)(b * SEQ + s_row)) * DIM + col) >> 1;
            outH[o] = pk2(O[nt][0] * inv0, O[nt][1] * inv0);
        }
        {
            size_t o = (((size_t)(b * SEQ + s_row + 8)) * DIM + col) >> 1;
            outH[o] = pk2(O[nt][2] * inv1, O[nt][3] * inv1);
        }
    }
}

// ---------------------------------------------------------------------------
extern "C" void kernel_launch(void* const* d_in, const int* in_sizes, int n_in,
                              void* d_out, int out_size)
{
    const float* x    = (const float*)d_in[0];
    const float* wq   = (const float*)d_in[1];
    const float* wk   = (const float*)d_in[2];
    const float* wv   = (const float*)d_in[3];
    const float* wo   = (const float*)d_in[4];
    const float* fcos = (const float*)d_in[5];
    const float* fsin = (const float*)d_in[6];
    float* out = (float*)d_out;

    float *qlin, *klin, *vlin;
    cudaGetSymbolAddress((void**)&qlin, g_qlin);
    cudaGetSymbolAddress((void**)&klin, g_klin);
    cudaGetSymbolAddress((void**)&vlin, g_vlin);

    __half *xh, *wqh, *wql, *wkh, *wkl, *wvh, *wvl, *woh, *wol, *ah;
    cudaGetSymbolAddress((void**)&xh,  g_xh);
    cudaGetSymbolAddress((void**)&wqh, g_wqh);
    cudaGetSymbolAddress((void**)&wql, g_wql);
    cudaGetSymbolAddress((void**)&wkh, g_wkh);
    cudaGetSymbolAddress((void**)&wkl, g_wkl);
    cudaGetSymbolAddress((void**)&wvh, g_wvh);
    cudaGetSymbolAddress((void**)&wvl, g_wvl);
    cudaGetSymbolAddress((void**)&woh, g_woh);
    cudaGetSymbolAddress((void**)&wol, g_wol);
    cudaGetSymbolAddress((void**)&ah,  g_ah);

    __half *Qh, *Kh, *Kl, *Vh, *Vl;
    cudaGetSymbolAddress((void**)&Qh, g_Qh);
    cudaGetSymbolAddress((void**)&Kh, g_Kh);
    cudaGetSymbolAddress((void**)&Kl, g_Kl);
    cudaGetSymbolAddress((void**)&Vh, g_Vh);
    cudaGetSymbolAddress((void**)&Vl, g_Vl);

    cudaFuncSetAttribute(gemm_mma_kernel,
                         cudaFuncAttributeMaxDynamicSharedMemorySize, GEMM_SMEM);
    cudaFuncSetAttribute(flash_mma_kernel,
                         cudaFuncAttributeMaxDynamicSharedMemorySize, FLASH_SMEM);

    const int nx4 = (MROWS * DIM) / 4;
    const int nw4 = (DIM * DIM) / 4;
    cvt_hi_kernel<<<(nx4 + 255) / 256, 256>>>((const float4*)x, (uint32_t*)xh, nx4);
    split_kernel<<<(nw4 + 255) / 256, 256>>>((const float4*)wq,
        (uint32_t*)wqh, (uint32_t*)wql, nw4);
    split_kernel<<<(nw4 + 255) / 256, 256>>>((const float4*)wk,
        (uint32_t*)wkh, (uint32_t*)wkl, nw4);
    split_kernel<<<(nw4 + 255) / 256, 256>>>((const float4*)wv,
        (uint32_t*)wvh, (uint32_t*)wvl, nw4);
    split_kernel<<<(nw4 + 255) / 256, 256>>>((const float4*)wo,
        (uint32_t*)woh, (uint32_t*)wol, nw4);

    dim3 gGrid(DIM / 128, MROWS / 128);
    gemm_mma_kernel<<<gGrid, 256, GEMM_SMEM>>>(xh, wqh, wql, qlin, MROWS, DIM, DIM);
    gemm_mma_kernel<<<gGrid, 256, GEMM_SMEM>>>(xh, wkh, wkl, klin, MROWS, DIM, DIM);
    gemm_mma_kernel<<<gGrid, 256, GEMM_SMEM>>>(xh, wvh, wvl, vlin, MROWS, DIM, DIM);

    int ropeElems = BSZ * SEQ * NH * (HD / 2);
    rope_split_kernel<<<ropeElems / 256, 256>>>(qlin, klin, vlin, fcos, fsin,
        (uint32_t*)Qh, (uint32_t*)Kh, (uint32_t*)Kl,
        (uint32_t*)Vh, (uint32_t*)Vl);

    flash_mma_kernel<<<dim3(BSZ * NH, SEQ / 128), 256, FLASH_SMEM>>>(
        Qh, Kh, Kl, Vh, Vl, (uint32_t*)ah);

    // output projection: A = attn hi only
    gemm_mma_kernel<<<gGrid, 256, GEMM_SMEM>>>(ah, woh, wol, out, MROWS, DIM, DIM);
}

// round 8
// speedup vs baseline: 7.6737x; 1.6964x over previous
#include <cuda_runtime.h>
#include <cuda_fp16.h>
#include <math.h>
#include <stdint.h>

#define BSZ 2
#define SEQ 2048
#define DIM 2048
#define NH  16
#define HD  128
#define MROWS (BSZ*SEQ)          // 4096

// ---------------- scratch (static device globals; no allocation) -----------
__device__ float g_qlin[(size_t)MROWS * DIM];
__device__ float g_klin[(size_t)MROWS * DIM];
__device__ float g_vlin[(size_t)MROWS * DIM];

// fp16 operands (hi only — 1-pass everywhere)
__device__ __half g_xh[(size_t)MROWS * DIM];
__device__ __half g_wqh[(size_t)DIM * DIM];
__device__ __half g_wkh[(size_t)DIM * DIM];
__device__ __half g_wvh[(size_t)DIM * DIM];
__device__ __half g_woh[(size_t)DIM * DIM];
__device__ __half g_ah[(size_t)MROWS * DIM];     // attention out

// per-head fp16 Q,K,V  [B*NH, SEQ, HD]
#define HELEMS ((size_t)BSZ * NH * SEQ * HD)
__device__ __half g_Qh[HELEMS];
__device__ __half g_Kh[HELEMS];
__device__ __half g_Vh[HELEMS];

// ======================= helpers ==========================================
__device__ __forceinline__ uint32_t smem_u32(const void* p) {
    uint32_t a;
    asm("{ .reg .u64 t; cvta.to.shared.u64 t, %1; cvt.u32.u64 %0, t; }"
        : "=r"(a) : "l"(p));
    return a;
}
__device__ __forceinline__ void cp16(uint32_t saddr, const void* g) {
    asm volatile("cp.async.ca.shared.global [%0], [%1], 16;"
                 :: "r"(saddr), "l"(g));
}
#define CP_COMMIT() asm volatile("cp.async.commit_group;" ::: "memory")
#define CP_WAIT(n)  asm volatile("cp.async.wait_group %0;" :: "n"(n) : "memory")

__device__ __forceinline__ void ldm_x4(uint32_t* d, uint32_t addr) {
    asm volatile("ldmatrix.sync.aligned.m8n8.x4.shared.b16 {%0,%1,%2,%3}, [%4];"
                 : "=r"(d[0]), "=r"(d[1]), "=r"(d[2]), "=r"(d[3]) : "r"(addr));
}
__device__ __forceinline__ void ldm_x4t(uint32_t* d, uint32_t addr) {
    asm volatile("ldmatrix.sync.aligned.m8n8.x4.trans.shared.b16 {%0,%1,%2,%3}, [%4];"
                 : "=r"(d[0]), "=r"(d[1]), "=r"(d[2]), "=r"(d[3]) : "r"(addr));
}
__device__ __forceinline__ void mma_f16(float* c, const uint32_t* a,
                                        uint32_t b0, uint32_t b1) {
    asm volatile(
        "mma.sync.aligned.m16n8k16.row.col.f32.f16.f16.f32 "
        "{%0,%1,%2,%3}, {%4,%5,%6,%7}, {%8,%9}, {%0,%1,%2,%3};"
        : "+f"(c[0]), "+f"(c[1]), "+f"(c[2]), "+f"(c[3])
        : "r"(a[0]), "r"(a[1]), "r"(a[2]), "r"(a[3]), "r"(b0), "r"(b1));
}
// pack {lo, hi} floats -> f16x2 (lo in low half)
__device__ __forceinline__ uint32_t pk2(float lo, float hi) {
    uint32_t r;
    asm("cvt.rn.f16x2.f32 %0, %1, %2;" : "=r"(r) : "f"(hi), "f"(lo));
    return r;
}

// =================== convert fp32 -> fp16 ==================================
__global__ __launch_bounds__(256) void cvt_hi_kernel(
    const float4* __restrict__ in, uint32_t* __restrict__ hi, int n4)
{
    int i = blockIdx.x * blockDim.x + threadIdx.x;
    if (i >= n4) return;
    float4 v = in[i];
    hi[2 * i]     = pk2(v.x, v.y);
    hi[2 * i + 1] = pk2(v.z, v.w);
}

// =============== mma.sync NT GEMM (1-pass fp16, fp32 accum) ================
// C = Ah*Bh  (both operands fp16-rounded)
#define GSTR 40                        // smem row stride in halves
#define TILEB (128 * GSTR * 2)         // 10240 bytes per operand tile
#define STAGEB (2 * TILEB)             // Ah,Bh = 20480 bytes
#define GEMM_SMEM (2 * STAGEB)         // 40960 bytes

__device__ __forceinline__ void gemm_load_chunk(
    uint32_t sbase,
    const __half* __restrict__ Ah, const __half* __restrict__ Bh,
    int row0, int col0, int k0, int Kdim, int tid)
{
#pragma unroll
    for (int i = 0; i < 2; ++i) {
        int v = tid + i * 256;
        int r = v >> 2, cv = v & 3;
        uint32_t soff = (uint32_t)(r * GSTR + cv * 8) * 2;
        size_t gA = (size_t)(row0 + r) * Kdim + k0 + cv * 8;
        size_t gB = (size_t)(col0 + r) * Kdim + k0 + cv * 8;
        cp16(sbase + soff,         Ah + gA);
        cp16(sbase + TILEB + soff, Bh + gB);
    }
}

__global__ __launch_bounds__(256) void gemm_mma_kernel(
    const __half* __restrict__ Ah, const __half* __restrict__ Bh,
    float* __restrict__ C, int Mdim, int Ndim, int Kdim)
{
    extern __shared__ char smem[];
    uint32_t sm0 = smem_u32(smem);

    const int tid  = threadIdx.x;
    const int wid  = tid >> 5;
    const int lane = tid & 31;
    const int wr = wid >> 2, wc = wid & 3;
    const int m0w = wr * 64, n0w = wc * 32;
    const int row0 = blockIdx.y * 128;
    const int col0 = blockIdx.x * 128;

    const int g  = lane >> 3;
    const int fr = (g & 1) * 8 + (lane & 7);
    const int fc = (g >> 1) * 8;

    float acc[4][4][4];
#pragma unroll
    for (int a = 0; a < 4; a++)
#pragma unroll
        for (int b = 0; b < 4; b++)
#pragma unroll
            for (int d = 0; d < 4; d++) acc[a][b][d] = 0.f;

    const int nchunk = Kdim / 32;

    gemm_load_chunk(sm0, Ah, Bh, row0, col0, 0, Kdim, tid);
    CP_COMMIT();

    for (int c = 0; c < nchunk; ++c) {
        if (c + 1 < nchunk) {
            gemm_load_chunk(sm0 + ((c + 1) & 1) * STAGEB, Ah, Bh,
                            row0, col0, (c + 1) * 32, Kdim, tid);
            CP_COMMIT();
            CP_WAIT(1);
        } else {
            CP_WAIT(0);
        }
        __syncthreads();

        uint32_t sb = sm0 + (c & 1) * STAGEB;
#pragma unroll
        for (int ks = 0; ks < 2; ++ks) {
            const int kb = ks * 16;
            uint32_t bh[2][4];
#pragma unroll
            for (int nt2 = 0; nt2 < 2; ++nt2) {
                uint32_t ba = sb + TILEB +
                    (uint32_t)((n0w + nt2 * 16 + fr) * GSTR + kb + fc) * 2;
                ldm_x4(bh[nt2], ba);
            }
#pragma unroll
            for (int mt = 0; mt < 4; ++mt) {
                uint32_t aa = sb +
                    (uint32_t)((m0w + mt * 16 + fr) * GSTR + kb + fc) * 2;
                uint32_t ah[4];
                ldm_x4(ah, aa);
#pragma unroll
                for (int nt = 0; nt < 4; ++nt) {
                    uint32_t b0h = bh[nt >> 1][nt & 1];
                    uint32_t b1h = bh[nt >> 1][2 + (nt & 1)];
                    mma_f16(acc[mt][nt], ah, b0h, b1h);
                }
            }
        }
        __syncthreads();
    }

#pragma unroll
    for (int mt = 0; mt < 4; ++mt) {
#pragma unroll
        for (int nt = 0; nt < 4; ++nt) {
            int r  = row0 + m0w + mt * 16 + (lane >> 2);
            int cc = col0 + n0w + nt * 8 + (lane & 3) * 2;
            float2 v0; v0.x = acc[mt][nt][0]; v0.y = acc[mt][nt][1];
            float2 v1; v1.x = acc[mt][nt][2]; v1.y = acc[mt][nt][3];
            *(float2*)&C[(size_t)r * Ndim + cc] = v0;
            *(float2*)&C[(size_t)(r + 8) * Ndim + cc] = v1;
        }
    }
}

// ------ RoPE + transpose to [B*H,S,HD] + convert fp16 ----------------------
__global__ __launch_bounds__(256) void rope_split_kernel(
    const float* __restrict__ qlin, const float* __restrict__ klin,
    const float* __restrict__ vlin,
    const float* __restrict__ cosT, const float* __restrict__ sinT,
    uint32_t* __restrict__ Qh, uint32_t* __restrict__ Kh,
    uint32_t* __restrict__ Vh)
{
    int idx = blockIdx.x * blockDim.x + threadIdx.x;
    const int HDH = HD / 2;
    int d2 = idx % HDH;
    int h  = (idx / HDH) % NH;
    int s  = (idx / (HDH * NH)) % SEQ;
    int b  = idx / (HDH * NH * SEQ);

    size_t src = ((size_t)(b * SEQ + s)) * DIM + h * HD + 2 * d2;
    float c  = cosT[s * HDH + d2];
    float sn = sinT[s * HDH + d2];
    size_t dst = ((((size_t)(b * NH + h)) * SEQ + s) * HD + 2 * d2) >> 1;

    float q0 = qlin[src], q1 = qlin[src + 1];
    float k0 = klin[src], k1 = klin[src + 1];
    float v0 = vlin[src], v1 = vlin[src + 1];

    Qh[dst] = pk2(q0 * c - q1 * sn, q0 * sn + q1 * c);
    Kh[dst] = pk2(k0 * c - k1 * sn, k0 * sn + k1 * c);
    Vh[dst] = pk2(v0, v1);
}

// ============= Flash attention via mma.sync (1-pass fp16) ==================
// CTA: 128 q-rows, 8 warps x 16 rows. BKV=64. double-buffered K/V.
#define FQS   272                  // smem row stride in BYTES (136 halves)
#define FB_QH 0
#define FB_ST 34816                // 128*272
#define FSTG  34816                // 2 * 64*272 (K + V)
#define FB_KH 0
#define FB_VH 17408
#define FLASH_SMEM (FB_ST + 2 * FSTG)   // 104448

__global__ __launch_bounds__(256, 1) void flash_mma_kernel(
    const __half* __restrict__ Qh, const __half* __restrict__ Kh,
    const __half* __restrict__ Vh, uint32_t* __restrict__ outH)
{
    extern __shared__ char smem[];
    uint32_t s0 = smem_u32(smem);
    const int bh  = blockIdx.x;
    const int qt  = (int)gridDim.y - 1 - (int)blockIdx.y;   // big tiles first
    const int tid = threadIdx.x, wid = tid >> 5, lane = tid & 31;
    const int m0w = wid * 16;
    const int gg  = lane >> 3;
    const int fr  = (gg & 1) * 8 + (lane & 7);
    const int fc  = (gg >> 1) * 8;
    const int q0  = qt * 128;
    const size_t hoff = (size_t)bh * SEQ * HD;
    const float scale = 0.08838834764831845f;   // 1/sqrt(128)

    {
        const __half* gq_h = Qh + hoff + (size_t)q0 * HD;
#pragma unroll
        for (int i = 0; i < 8; i++) {
            int v = tid + (i << 8); int r = v >> 4, c = v & 15;
            uint32_t so = (uint32_t)(r * FQS + c * 16);
            cp16(s0 + FB_QH + so, gq_h + r * HD + c * 8);
        }
        uint32_t sb = s0 + FB_ST;
#pragma unroll
        for (int i = 0; i < 4; i++) {
            int v = tid + (i << 8); int r = v >> 4, c = v & 15;
            uint32_t so = (uint32_t)(r * FQS + c * 16);
            size_t go = hoff + r * HD + c * 8;
            cp16(sb + FB_KH + so, Kh + go);
            cp16(sb + FB_VH + so, Vh + go);
        }
    }
    CP_COMMIT();

    float O[16][4];
#pragma unroll
    for (int i = 0; i < 16; i++)
#pragma unroll
        for (int j = 0; j < 4; j++) O[i][j] = 0.f;
    float m0 = -1e30f, m1 = -1e30f, l0 = 0.f, l1 = 0.f;

    const int last  = 2 * qt + 1;
    const int r0g   = q0 + m0w + (lane >> 2);
    const int cbase = (lane & 3) * 2;

    for (int kt = 0; kt <= last; kt++) {
        const int stg = kt & 1;
        if (kt < last) {
            uint32_t sb = s0 + FB_ST + (stg ^ 1) * FSTG;
            size_t kvo = hoff + (size_t)(kt + 1) * 64 * HD;
#pragma unroll
            for (int i = 0; i < 4; i++) {
                int v = tid + (i << 8); int r = v >> 4, c = v & 15;
                uint32_t so = (uint32_t)(r * FQS + c * 16);
                size_t go = kvo + r * HD + c * 8;
                cp16(sb + FB_KH + so, Kh + go);
                cp16(sb + FB_VH + so, Vh + go);
            }
            CP_COMMIT();
            CP_WAIT(1);
        } else {
            CP_WAIT(0);
        }
        __syncthreads();

        uint32_t sb = s0 + FB_ST + stg * FSTG;

        // ---- S = Q K^T (1-pass) ----
        float Sv[8][4];
#pragma unroll
        for (int i = 0; i < 8; i++)
#pragma unroll
            for (int j = 0; j < 4; j++) Sv[i][j] = 0.f;

#pragma unroll
        for (int kk = 0; kk < 8; kk++) {
            uint32_t qoff = (uint32_t)((m0w + fr) * FQS + (kk * 16 + fc) * 2);
            uint32_t ah[4];
            ldm_x4(ah, s0 + FB_QH + qoff);
#pragma unroll
            for (int nt2 = 0; nt2 < 4; nt2++) {
                uint32_t koff = (uint32_t)((nt2 * 16 + fr) * FQS + (kk * 16 + fc) * 2);
                uint32_t bh4[4];
                ldm_x4(bh4, sb + FB_KH + koff);
                mma_f16(Sv[2 * nt2],     ah, bh4[0], bh4[2]);
                mma_f16(Sv[2 * nt2 + 1], ah, bh4[1], bh4[3]);
            }
        }

        // ---- scale + causal mask ----
        if (kt >= 2 * qt) {
#pragma unroll
            for (int nt = 0; nt < 8; nt++) {
                int c0 = kt * 64 + nt * 8 + cbase;
                Sv[nt][0] = (c0     > r0g)     ? -1e30f : Sv[nt][0] * scale;
                Sv[nt][1] = (c0 + 1 > r0g)     ? -1e30f : Sv[nt][1] * scale;
                Sv[nt][2] = (c0     > r0g + 8) ? -1e30f : Sv[nt][2] * scale;
                Sv[nt][3] = (c0 + 1 > r0g + 8) ? -1e30f : Sv[nt][3] * scale;
            }
        } else {
#pragma unroll
            for (int nt = 0; nt < 8; nt++)
#pragma unroll
                for (int j = 0; j < 4; j++) Sv[nt][j] *= scale;
        }

        // ---- online softmax (rows r0g and r0g+8, 4 lanes each) ----
        float mx0 = -1e30f, mx1 = -1e30f;
#pragma unroll
        for (int nt = 0; nt < 8; nt++) {
            mx0 = fmaxf(mx0, fmaxf(Sv[nt][0], Sv[nt][1]));
            mx1 = fmaxf(mx1, fmaxf(Sv[nt][2], Sv[nt][3]));
        }
        mx0 = fmaxf(mx0, __shfl_xor_sync(0xffffffffu, mx0, 1));
        mx0 = fmaxf(mx0, __shfl_xor_sync(0xffffffffu, mx0, 2));
        mx1 = fmaxf(mx1, __shfl_xor_sync(0xffffffffu, mx1, 1));
        mx1 = fmaxf(mx1, __shfl_xor_sync(0xffffffffu, mx1, 2));

        float mn0 = fmaxf(m0, mx0), mn1 = fmaxf(m1, mx1);
        float al0 = __expf(m0 - mn0), al1 = __expf(m1 - mn1);
        float sum0 = 0.f, sum1 = 0.f;
#pragma unroll
        for (int nt = 0; nt < 8; nt++) {
            Sv[nt][0] = __expf(Sv[nt][0] - mn0); sum0 += Sv[nt][0];
            Sv[nt][1] = __expf(Sv[nt][1] - mn0); sum0 += Sv[nt][1];
            Sv[nt][2] = __expf(Sv[nt][2] - mn1); sum1 += Sv[nt][2];
            Sv[nt][3] = __expf(Sv[nt][3] - mn1); sum1 += Sv[nt][3];
        }
        sum0 += __shfl_xor_sync(0xffffffffu, sum0, 1);
        sum0 += __shfl_xor_sync(0xffffffffu, sum0, 2);
        sum1 += __shfl_xor_sync(0xffffffffu, sum1, 1);
        sum1 += __shfl_xor_sync(0xffffffffu, sum1, 2);
        l0 = l0 * al0 + sum0; l1 = l1 * al1 + sum1;
        m0 = mn0; m1 = mn1;
#pragma unroll
        for (int nt = 0; nt < 16; nt++) {
            O[nt][0] *= al0; O[nt][1] *= al0;
            O[nt][2] *= al1; O[nt][3] *= al1;
        }

        // ---- O += P V (1-pass) ----
#pragma unroll
        for (int kk = 0; kk < 4; kk++) {
            uint32_t pah[4];
            pah[0] = pk2(Sv[2 * kk][0],     Sv[2 * kk][1]);
            pah[1] = pk2(Sv[2 * kk][2],     Sv[2 * kk][3]);
            pah[2] = pk2(Sv[2 * kk + 1][0], Sv[2 * kk + 1][1]);
            pah[3] = pk2(Sv[2 * kk + 1][2], Sv[2 * kk + 1][3]);
#pragma unroll
            for (int j = 0; j < 8; j++) {
                uint32_t vo = (uint32_t)((kk * 16 + fr) * FQS + (j * 16 + fc) * 2);
                uint32_t vh4[4];
                ldm_x4t(vh4, sb + FB_VH + vo);
                mma_f16(O[2 * j],     pah, vh4[0], vh4[1]);
                mma_f16(O[2 * j + 1], pah, vh4[2], vh4[3]);
            }
        }
        __syncthreads();
    }

    // ---- epilogue: normalize, store fp16 to [B,S,DIM] ----
    float inv0 = 1.f / l0, inv1 = 1.f / l1;
    const int b = bh >> 4, h = bh & 15;
    const int s_row = q0 + m0w + (lane >> 2);
#pragma unroll
    for (int nt = 0; nt < 16; nt++) {
        int col = h * HD + nt * 8 + cbase;
        {
            size_t o = (((size_t)(b * SEQ + s_row)) * DIM + col) >> 1;
            outH[o] = pk2(O[nt][0] * inv0, O[nt][1] * inv0);
        }
        {
            size_t o = (((size_t)(b * SEQ + s_row + 8)) * DIM + col) >> 1;
            outH[o] = pk2(O[nt][2] * inv1, O[nt][3] * inv1);
        }
    }
}

// ---------------------------------------------------------------------------
extern "C" void kernel_launch(void* const* d_in, const int* in_sizes, int n_in,
                              void* d_out, int out_size)
{
    const float* x    = (const float*)d_in[0];
    const float* wq   = (const float*)d_in[1];
    const float* wk   = (const float*)d_in[2];
    const float* wv   = (const float*)d_in[3];
    const float* wo   = (const float*)d_in[4];
    const float* fcos = (const float*)d_in[5];
    const float* fsin = (const float*)d_in[6];
    float* out = (float*)d_out;

    float *qlin, *klin, *vlin;
    cudaGetSymbolAddress((void**)&qlin, g_qlin);
    cudaGetSymbolAddress((void**)&klin, g_klin);
    cudaGetSymbolAddress((void**)&vlin, g_vlin);

    __half *xh, *wqh, *wkh, *wvh, *woh, *ah;
    cudaGetSymbolAddress((void**)&xh,  g_xh);
    cudaGetSymbolAddress((void**)&wqh, g_wqh);
    cudaGetSymbolAddress((void**)&wkh, g_wkh);
    cudaGetSymbolAddress((void**)&wvh, g_wvh);
    cudaGetSymbolAddress((void**)&woh, g_woh);
    cudaGetSymbolAddress((void**)&ah,  g_ah);

    __half *Qh, *Kh, *Vh;
    cudaGetSymbolAddress((void**)&Qh, g_Qh);
    cudaGetSymbolAddress((void**)&Kh, g_Kh);
    cudaGetSymbolAddress((void**)&Vh, g_Vh);

    cudaFuncSetAttribute(gemm_mma_kernel,
                         cudaFuncAttributeMaxDynamicSharedMemorySize, GEMM_SMEM);
    cudaFuncSetAttribute(flash_mma_kernel,
                         cudaFuncAttributeMaxDynamicSharedMemorySize, FLASH_SMEM);

    const int nx4 = (MROWS * DIM) / 4;
    const int nw4 = (DIM * DIM) / 4;
    cvt_hi_kernel<<<(nx4 + 255) / 256, 256>>>((const float4*)x,  (uint32_t*)xh,  nx4);
    cvt_hi_kernel<<<(nw4 + 255) / 256, 256>>>((const float4*)wq, (uint32_t*)wqh, nw4);
    cvt_hi_kernel<<<(nw4 + 255) / 256, 256>>>((const float4*)wk, (uint32_t*)wkh, nw4);
    cvt_hi_kernel<<<(nw4 + 255) / 256, 256>>>((const float4*)wv, (uint32_t*)wvh, nw4);
    cvt_hi_kernel<<<(nw4 + 255) / 256, 256>>>((const float4*)wo, (uint32_t*)woh, nw4);

    dim3 gGrid(DIM / 128, MROWS / 128);
    gemm_mma_kernel<<<gGrid, 256, GEMM_SMEM>>>(xh, wqh, qlin, MROWS, DIM, DIM);
    gemm_mma_kernel<<<gGrid, 256, GEMM_SMEM>>>(xh, wkh, klin, MROWS, DIM, DIM);
    gemm_mma_kernel<<<gGrid, 256, GEMM_SMEM>>>(xh, wvh, vlin, MROWS, DIM, DIM);

    int ropeElems = BSZ * SEQ * NH * (HD / 2);
    rope_split_kernel<<<ropeElems / 256, 256>>>(qlin, klin, vlin, fcos, fsin,
        (uint32_t*)Qh, (uint32_t*)Kh, (uint32_t*)Vh);

    flash_mma_kernel<<<dim3(BSZ * NH, SEQ / 128), 256, FLASH_SMEM>>>(
        Qh, Kh, Vh, (uint32_t*)ah);

    gemm_mma_kernel<<<gGrid, 256, GEMM_SMEM>>>(ah, woh, out, MROWS, DIM, DIM);
}

// round 9
// speedup vs baseline: 7.8288x; 1.0202x over previous
#include <cuda_runtime.h>
#include <cuda_fp16.h>
#include <math.h>
#include <stdint.h>

#define BSZ 2
#define SEQ 2048
#define DIM 2048
#define NH  16
#define HD  128
#define MROWS (BSZ*SEQ)          // 4096

// ---------------- scratch (static device globals; no allocation) -----------
__device__ __half g_xh[(size_t)MROWS * DIM];
__device__ __half g_wqh[(size_t)DIM * DIM];
__device__ __half g_wkh[(size_t)DIM * DIM];
__device__ __half g_wvh[(size_t)DIM * DIM];
__device__ __half g_woh[(size_t)DIM * DIM];
__device__ __half g_ah[(size_t)MROWS * DIM];     // attention out [B,S,DIM]

// per-head fp16 Q,K,V  [B*NH, SEQ, HD]
#define HELEMS ((size_t)BSZ * NH * SEQ * HD)
__device__ __half g_Qh[HELEMS];
__device__ __half g_Kh[HELEMS];
__device__ __half g_Vh[HELEMS];

// ======================= helpers ==========================================
__device__ __forceinline__ uint32_t smem_u32(const void* p) {
    uint32_t a;
    asm("{ .reg .u64 t; cvta.to.shared.u64 t, %1; cvt.u32.u64 %0, t; }"
        : "=r"(a) : "l"(p));
    return a;
}
__device__ __forceinline__ void cp16(uint32_t saddr, const void* g) {
    asm volatile("cp.async.ca.shared.global [%0], [%1], 16;"
                 :: "r"(saddr), "l"(g));
}
#define CP_COMMIT() asm volatile("cp.async.commit_group;" ::: "memory")
#define CP_WAIT(n)  asm volatile("cp.async.wait_group %0;" :: "n"(n) : "memory")

__device__ __forceinline__ void ldm_x4(uint32_t* d, uint32_t addr) {
    asm volatile("ldmatrix.sync.aligned.m8n8.x4.shared.b16 {%0,%1,%2,%3}, [%4];"
                 : "=r"(d[0]), "=r"(d[1]), "=r"(d[2]), "=r"(d[3]) : "r"(addr));
}
__device__ __forceinline__ void ldm_x4t(uint32_t* d, uint32_t addr) {
    asm volatile("ldmatrix.sync.aligned.m8n8.x4.trans.shared.b16 {%0,%1,%2,%3}, [%4];"
                 : "=r"(d[0]), "=r"(d[1]), "=r"(d[2]), "=r"(d[3]) : "r"(addr));
}
__device__ __forceinline__ void mma_f16(float* c, const uint32_t* a,
                                        uint32_t b0, uint32_t b1) {
    asm volatile(
        "mma.sync.aligned.m16n8k16.row.col.f32.f16.f16.f32 "
        "{%0,%1,%2,%3}, {%4,%5,%6,%7}, {%8,%9}, {%0,%1,%2,%3};"
        : "+f"(c[0]), "+f"(c[1]), "+f"(c[2]), "+f"(c[3])
        : "r"(a[0]), "r"(a[1]), "r"(a[2]), "r"(a[3]), "r"(b0), "r"(b1));
}
// pack {lo, hi} floats -> f16x2 (lo in low half)
__device__ __forceinline__ uint32_t pk2(float lo, float hi) {
    uint32_t r;
    asm("cvt.rn.f16x2.f32 %0, %1, %2;" : "=r"(r) : "f"(hi), "f"(lo));
    return r;
}

// =================== convert fp32 -> fp16 ==================================
__global__ __launch_bounds__(256) void cvt_hi_kernel(
    const float4* __restrict__ in, uint32_t* __restrict__ hi, int n4)
{
    int i = blockIdx.x * blockDim.x + threadIdx.x;
    if (i >= n4) return;
    float4 v = in[i];
    hi[2 * i]     = pk2(v.x, v.y);
    hi[2 * i + 1] = pk2(v.z, v.w);
}

// all 4 weights in one launch (blockIdx.y selects the matrix)
__global__ __launch_bounds__(256) void cvt_w4_kernel(
    const float4* __restrict__ w0, const float4* __restrict__ w1,
    const float4* __restrict__ w2, const float4* __restrict__ w3,
    uint32_t* __restrict__ o0, uint32_t* __restrict__ o1,
    uint32_t* __restrict__ o2, uint32_t* __restrict__ o3, int n4)
{
    int i = blockIdx.x * blockDim.x + threadIdx.x;
    if (i >= n4) return;
    const float4* in; uint32_t* hi;
    switch (blockIdx.y) {
        case 0:  in = w0; hi = o0; break;
        case 1:  in = w1; hi = o1; break;
        case 2:  in = w2; hi = o2; break;
        default: in = w3; hi = o3; break;
    }
    float4 v = in[i];
    hi[2 * i]     = pk2(v.x, v.y);
    hi[2 * i + 1] = pk2(v.z, v.w);
}

// =============== mma.sync NT GEMM (1-pass fp16, fp32 accum) ================
// MODE 0: C fp32 [M, N]            (output projection -> d_out)
// MODE 1: rope + fp16 -> [B*H,S,HD] (Q/K projections)
// MODE 2: fp16 -> [B*H,S,HD]        (V projection)
#define GSTR 40                        // smem row stride in halves
#define TILEB (128 * GSTR * 2)         // 10240 bytes per operand tile
#define STAGEB (2 * TILEB)             // Ah,Bh = 20480 bytes
#define GEMM_SMEM (2 * STAGEB)         // 40960 bytes

__device__ __forceinline__ void gemm_load_chunk(
    uint32_t sbase,
    const __half* __restrict__ Ah, const __half* __restrict__ Bh,
    int row0, int col0, int k0, int tid)
{
#pragma unroll
    for (int i = 0; i < 2; ++i) {
        int v = tid + i * 256;
        int r = v >> 2, cv = v & 3;
        uint32_t soff = (uint32_t)(r * GSTR + cv * 8) * 2;
        size_t gA = (size_t)(row0 + r) * DIM + k0 + cv * 8;
        size_t gB = (size_t)(col0 + r) * DIM + k0 + cv * 8;
        cp16(sbase + soff,         Ah + gA);
        cp16(sbase + TILEB + soff, Bh + gB);
    }
}

template<int MODE>
__global__ __launch_bounds__(256) void gemm_mma_kernel(
    const __half* __restrict__ Ah, const __half* __restrict__ Bh,
    float* __restrict__ C, uint32_t* __restrict__ O16,
    const float* __restrict__ cosT, const float* __restrict__ sinT)
{
    extern __shared__ char smem[];
    uint32_t sm0 = smem_u32(smem);

    const int tid  = threadIdx.x;
    const int wid  = tid >> 5;
    const int lane = tid & 31;
    const int wr = wid >> 2, wc = wid & 3;
    const int m0w = wr * 64, n0w = wc * 32;
    const int row0 = blockIdx.y * 128;
    const int col0 = blockIdx.x * 128;

    const int g  = lane >> 3;
    const int fr = (g & 1) * 8 + (lane & 7);
    const int fc = (g >> 1) * 8;

    float acc[4][4][4];
#pragma unroll
    for (int a = 0; a < 4; a++)
#pragma unroll
        for (int b = 0; b < 4; b++)
#pragma unroll
            for (int d = 0; d < 4; d++) acc[a][b][d] = 0.f;

    const int nchunk = DIM / 32;

    gemm_load_chunk(sm0, Ah, Bh, row0, col0, 0, tid);
    CP_COMMIT();

    for (int c = 0; c < nchunk; ++c) {
        if (c + 1 < nchunk) {
            gemm_load_chunk(sm0 + ((c + 1) & 1) * STAGEB, Ah, Bh,
                            row0, col0, (c + 1) * 32, tid);
            CP_COMMIT();
            CP_WAIT(1);
        } else {
            CP_WAIT(0);
        }
        __syncthreads();

        uint32_t sb = sm0 + (c & 1) * STAGEB;
#pragma unroll
        for (int ks = 0; ks < 2; ++ks) {
            const int kb = ks * 16;
            uint32_t bh[2][4];
#pragma unroll
            for (int nt2 = 0; nt2 < 2; ++nt2) {
                uint32_t ba = sb + TILEB +
                    (uint32_t)((n0w + nt2 * 16 + fr) * GSTR + kb + fc) * 2;
                ldm_x4(bh[nt2], ba);
            }
#pragma unroll
            for (int mt = 0; mt < 4; ++mt) {
                uint32_t aa = sb +
                    (uint32_t)((m0w + mt * 16 + fr) * GSTR + kb + fc) * 2;
                uint32_t ah[4];
                ldm_x4(ah, aa);
#pragma unroll
                for (int nt = 0; nt < 4; ++nt) {
                    uint32_t b0h = bh[nt >> 1][nt & 1];
                    uint32_t b1h = bh[nt >> 1][2 + (nt & 1)];
                    mma_f16(acc[mt][nt], ah, b0h, b1h);
                }
            }
        }
        __syncthreads();
    }

    // ------------------------------ epilogue -------------------------------
#pragma unroll
    for (int mt = 0; mt < 4; ++mt) {
#pragma unroll
        for (int nt = 0; nt < 4; ++nt) {
            int r  = row0 + m0w + mt * 16 + (lane >> 2);
            int cc = col0 + n0w + nt * 8 + (lane & 3) * 2;
            if (MODE == 0) {
                float2 v0; v0.x = acc[mt][nt][0]; v0.y = acc[mt][nt][1];
                float2 v1; v1.x = acc[mt][nt][2]; v1.y = acc[mt][nt][3];
                *(float2*)&C[(size_t)r * DIM + cc] = v0;
                *(float2*)&C[(size_t)(r + 8) * DIM + cc] = v1;
            } else {
                const int h  = cc >> 7;          // head (col tile = 1 head)
                const int hc = cc & 127;         // col within head (even)
                const int d2 = hc >> 1;
#pragma unroll
                for (int rr = 0; rr < 2; ++rr) {
                    int row = r + rr * 8;
                    int b = row >> 11, s = row & (SEQ - 1);
                    float v0 = acc[mt][nt][2 * rr], v1 = acc[mt][nt][2 * rr + 1];
                    size_t dst = ((((size_t)(b * NH + h)) * SEQ + s) * HD + hc) >> 1;
                    if (MODE == 1) {
                        float co = cosT[s * (HD / 2) + d2];
                        float sn = sinT[s * (HD / 2) + d2];
                        O16[dst] = pk2(v0 * co - v1 * sn, v0 * sn + v1 * co);
                    } else {
                        O16[dst] = pk2(v0, v1);
                    }
                }
            }
        }
    }
}

// ============= Flash attention via mma.sync (1-pass fp16) ==================
// CTA: 128 q-rows, 8 warps x 16 rows. BKV=64. double-buffered K/V. 2 CTA/SM.
#define FQS   272                  // smem row stride in BYTES (136 halves)
#define FB_QH 0
#define FB_ST 34816                // 128*272
#define FSTG  34816                // 2 * 64*272 (K + V)
#define FB_KH 0
#define FB_VH 17408
#define FLASH_SMEM (FB_ST + 2 * FSTG)   // 104448

__global__ __launch_bounds__(256, 2) void flash_mma_kernel(
    const __half* __restrict__ Qh, const __half* __restrict__ Kh,
    const __half* __restrict__ Vh, uint32_t* __restrict__ outH)
{
    extern __shared__ char smem[];
    uint32_t s0 = smem_u32(smem);
    const int bh  = blockIdx.x;
    const int qt  = (int)gridDim.y - 1 - (int)blockIdx.y;   // big tiles first
    const int tid = threadIdx.x, wid = tid >> 5, lane = tid & 31;
    const int m0w = wid * 16;
    const int gg  = lane >> 3;
    const int fr  = (gg & 1) * 8 + (lane & 7);
    const int fc  = (gg >> 1) * 8;
    const int q0  = qt * 128;
    const size_t hoff = (size_t)bh * SEQ * HD;
    const float scale = 0.08838834764831845f;   // 1/sqrt(128)

    {
        const __half* gq_h = Qh + hoff + (size_t)q0 * HD;
#pragma unroll
        for (int i = 0; i < 8; i++) {
            int v = tid + (i << 8); int r = v >> 4, c = v & 15;
            uint32_t so = (uint32_t)(r * FQS + c * 16);
            cp16(s0 + FB_QH + so, gq_h + r * HD + c * 8);
        }
        uint32_t sb = s0 + FB_ST;
#pragma unroll
        for (int i = 0; i < 4; i++) {
            int v = tid + (i << 8); int r = v >> 4, c = v & 15;
            uint32_t so = (uint32_t)(r * FQS + c * 16);
            size_t go = hoff + r * HD + c * 8;
            cp16(sb + FB_KH + so, Kh + go);
            cp16(sb + FB_VH + so, Vh + go);
        }
    }
    CP_COMMIT();

    float O[16][4];
#pragma unroll
    for (int i = 0; i < 16; i++)
#pragma unroll
        for (int j = 0; j < 4; j++) O[i][j] = 0.f;
    float m0 = -1e30f, m1 = -1e30f, l0 = 0.f, l1 = 0.f;

    const int last  = 2 * qt + 1;
    const int r0g   = q0 + m0w + (lane >> 2);
    const int cbase = (lane & 3) * 2;

    for (int kt = 0; kt <= last; kt++) {
        const int stg = kt & 1;
        if (kt < last) {
            uint32_t sb = s0 + FB_ST + (stg ^ 1) * FSTG;
            size_t kvo = hoff + (size_t)(kt + 1) * 64 * HD;
#pragma unroll
            for (int i = 0; i < 4; i++) {
                int v = tid + (i << 8); int r = v >> 4, c = v & 15;
                uint32_t so = (uint32_t)(r * FQS + c * 16);
                size_t go = kvo + r * HD + c * 8;
                cp16(sb + FB_KH + so, Kh + go);
                cp16(sb + FB_VH + so, Vh + go);
            }
            CP_COMMIT();
            CP_WAIT(1);
        } else {
            CP_WAIT(0);
        }
        __syncthreads();

        uint32_t sb = s0 + FB_ST + stg * FSTG;

        // ---- S = Q K^T (1-pass) ----
        float Sv[8][4];
#pragma unroll
        for (int i = 0; i < 8; i++)
#pragma unroll
            for (int j = 0; j < 4; j++) Sv[i][j] = 0.f;

#pragma unroll
        for (int kk = 0; kk < 8; kk++) {
            uint32_t qoff = (uint32_t)((m0w + fr) * FQS + (kk * 16 + fc) * 2);
            uint32_t ah[4];
            ldm_x4(ah, s0 + FB_QH + qoff);
#pragma unroll
            for (int nt2 = 0; nt2 < 4; nt2++) {
                uint32_t koff = (uint32_t)((nt2 * 16 + fr) * FQS + (kk * 16 + fc) * 2);
                uint32_t bh4[4];
                ldm_x4(bh4, sb + FB_KH + koff);
                mma_f16(Sv[2 * nt2],     ah, bh4[0], bh4[2]);
                mma_f16(Sv[2 * nt2 + 1], ah, bh4[1], bh4[3]);
            }
        }

        // ---- scale + causal mask ----
        if (kt >= 2 * qt) {
#pragma unroll
            for (int nt = 0; nt < 8; nt++) {
                int c0 = kt * 64 + nt * 8 + cbase;
                Sv[nt][0] = (c0     > r0g)     ? -1e30f : Sv[nt][0] * scale;
                Sv[nt][1] = (c0 + 1 > r0g)     ? -1e30f : Sv[nt][1] * scale;
                Sv[nt][2] = (c0     > r0g + 8) ? -1e30f : Sv[nt][2] * scale;
                Sv[nt][3] = (c0 + 1 > r0g + 8) ? -1e30f : Sv[nt][3] * scale;
            }
        } else {
#pragma unroll
            for (int nt = 0; nt < 8; nt++)
#pragma unroll
                for (int j = 0; j < 4; j++) Sv[nt][j] *= scale;
        }

        // ---- online softmax (rows r0g and r0g+8, 4 lanes each) ----
        float mx0 = -1e30f, mx1 = -1e30f;
#pragma unroll
        for (int nt = 0; nt < 8; nt++) {
            mx0 = fmaxf(mx0, fmaxf(Sv[nt][0], Sv[nt][1]));
            mx1 = fmaxf(mx1, fmaxf(Sv[nt][2], Sv[nt][3]));
        }
        mx0 = fmaxf(mx0, __shfl_xor_sync(0xffffffffu, mx0, 1));
        mx0 = fmaxf(mx0, __shfl_xor_sync(0xffffffffu, mx0, 2));
        mx1 = fmaxf(mx1, __shfl_xor_sync(0xffffffffu, mx1, 1));
        mx1 = fmaxf(mx1, __shfl_xor_sync(0xffffffffu, mx1, 2));

        float mn0 = fmaxf(m0, mx0), mn1 = fmaxf(m1, mx1);
        float al0 = __expf(m0 - mn0), al1 = __expf(m1 - mn1);
        float sum0 = 0.f, sum1 = 0.f;
#pragma unroll
        for (int nt = 0; nt < 8; nt++) {
            Sv[nt][0] = __expf(Sv[nt][0] - mn0); sum0 += Sv[nt][0];
            Sv[nt][1] = __expf(Sv[nt][1] - mn0); sum0 += Sv[nt][1];
            Sv[nt][2] = __expf(Sv[nt][2] - mn1); sum1 += Sv[nt][2];
            Sv[nt][3] = __expf(Sv[nt][3] - mn1); sum1 += Sv[nt][3];
        }
        sum0 += __shfl_xor_sync(0xffffffffu, sum0, 1);
        sum0 += __shfl_xor_sync(0xffffffffu, sum0, 2);
        sum1 += __shfl_xor_sync(0xffffffffu, sum1, 1);
        sum1 += __shfl_xor_sync(0xffffffffu, sum1, 2);
        l0 = l0 * al0 + sum0; l1 = l1 * al1 + sum1;
        m0 = mn0; m1 = mn1;
#pragma unroll
        for (int nt = 0; nt < 16; nt++) {
            O[nt][0] *= al0; O[nt][1] *= al0;
            O[nt][2] *= al1; O[nt][3] *= al1;
        }

        // ---- O += P V (1-pass) ----
#pragma unroll
        for (int kk = 0; kk < 4; kk++) {
            uint32_t pah[4];
            pah[0] = pk2(Sv[2 * kk][0],     Sv[2 * kk][1]);
            pah[1] = pk2(Sv[2 * kk][2],     Sv[2 * kk][3]);
            pah[2] = pk2(Sv[2 * kk + 1][0], Sv[2 * kk + 1][1]);
            pah[3] = pk2(Sv[2 * kk + 1][2], Sv[2 * kk + 1][3]);
#pragma unroll
            for (int j = 0; j < 8; j++) {
                uint32_t vo = (uint32_t)((kk * 16 + fr) * FQS + (j * 16 + fc) * 2);
                uint32_t vh4[4];
                ldm_x4t(vh4, sb + FB_VH + vo);
                mma_f16(O[2 * j],     pah, vh4[0], vh4[1]);
                mma_f16(O[2 * j + 1], pah, vh4[2], vh4[3]);
            }
        }
        __syncthreads();
    }

    // ---- epilogue: normalize, store fp16 to [B,S,DIM] ----
    float inv0 = 1.f / l0, inv1 = 1.f / l1;
    const int b = bh >> 4, h = bh & 15;
    const int s_row = q0 + m0w + (lane >> 2);
#pragma unroll
    for (int nt = 0; nt < 16; nt++) {
        int col = h * HD + nt * 8 + cbase;
        {
            size_t o = (((size_t)(b * SEQ + s_row)) * DIM + col) >> 1;
            outH[o] = pk2(O[nt][0] * inv0, O[nt][1] * inv0);
        }
        {
            size_t o = (((size_t)(b * SEQ + s_row + 8)) * DIM + col) >> 1;
            outH[o] = pk2(O[nt][2] * inv1, O[nt][3] * inv1);
        }
    }
}

// ---------------------------------------------------------------------------
extern "C" void kernel_launch(void* const* d_in, const int* in_sizes, int n_in,
                              void* d_out, int out_size)
{
    const float* x    = (const float*)d_in[0];
    const float* wq   = (const float*)d_in[1];
    const float* wk   = (const float*)d_in[2];
    const float* wv   = (const float*)d_in[3];
    const float* wo   = (const float*)d_in[4];
    const float* fcos = (const float*)d_in[5];
    const float* fsin = (const float*)d_in[6];
    float* out = (float*)d_out;

    __half *xh, *wqh, *wkh, *wvh, *woh, *ah;
    cudaGetSymbolAddress((void**)&xh,  g_xh);
    cudaGetSymbolAddress((void**)&wqh, g_wqh);
    cudaGetSymbolAddress((void**)&wkh, g_wkh);
    cudaGetSymbolAddress((void**)&wvh, g_wvh);
    cudaGetSymbolAddress((void**)&woh, g_woh);
    cudaGetSymbolAddress((void**)&ah,  g_ah);

    __half *Qh, *Kh, *Vh;
    cudaGetSymbolAddress((void**)&Qh, g_Qh);
    cudaGetSymbolAddress((void**)&Kh, g_Kh);
    cudaGetSymbolAddress((void**)&Vh, g_Vh);

    cudaFuncSetAttribute(gemm_mma_kernel<0>,
                         cudaFuncAttributeMaxDynamicSharedMemorySize, GEMM_SMEM);
    cudaFuncSetAttribute(gemm_mma_kernel<1>,
                         cudaFuncAttributeMaxDynamicSharedMemorySize, GEMM_SMEM);
    cudaFuncSetAttribute(gemm_mma_kernel<2>,
                         cudaFuncAttributeMaxDynamicSharedMemorySize, GEMM_SMEM);
    cudaFuncSetAttribute(flash_mma_kernel,
                         cudaFuncAttributeMaxDynamicSharedMemorySize, FLASH_SMEM);

    const int nx4 = (MROWS * DIM) / 4;
    const int nw4 = (DIM * DIM) / 4;
    cvt_hi_kernel<<<(nx4 + 255) / 256, 256>>>((const float4*)x, (uint32_t*)xh, nx4);
    cvt_w4_kernel<<<dim3((nw4 + 255) / 256, 4), 256>>>(
        (const float4*)wq, (const float4*)wk, (const float4*)wv, (const float4*)wo,
        (uint32_t*)wqh, (uint32_t*)wkh, (uint32_t*)wvh, (uint32_t*)woh, nw4);

    dim3 gGrid(DIM / 128, MROWS / 128);
    // Q, K: fused rope epilogue -> per-head fp16
    gemm_mma_kernel<1><<<gGrid, 256, GEMM_SMEM>>>(xh, wqh, nullptr, (uint32_t*)Qh, fcos, fsin);
    gemm_mma_kernel<1><<<gGrid, 256, GEMM_SMEM>>>(xh, wkh, nullptr, (uint32_t*)Kh, fcos, fsin);
    // V: fp16 convert epilogue -> per-head fp16
    gemm_mma_kernel<2><<<gGrid, 256, GEMM_SMEM>>>(xh, wvh, nullptr, (uint32_t*)Vh, nullptr, nullptr);

    flash_mma_kernel<<<dim3(BSZ * NH, SEQ / 128), 256, FLASH_SMEM>>>(
        Qh, Kh, Vh, (uint32_t*)ah);

    // output projection -> fp32 d_out
    gemm_mma_kernel<0><<<gGrid, 256, GEMM_SMEM>>>(ah, woh, out, nullptr, nullptr, nullptr);
}